// round 1
// baseline (speedup 1.0000x reference)
#include <cuda_runtime.h>

// ---------------- problem constants ----------------
#define Bsz 2
#define Hf 128
#define Wf 128
#define Cc 64
#define hh 64
#define ww 64
#define Ll 4096          // hh*ww
#define KK 576           // 3*3*64
#define Y_ELEMS (Bsz*Hf*Wf*Cc)        // 2097152
#define ATT_PER_B ((size_t)Ll*Ll)     // 16777216

// ---------------- scratch (static device globals; no allocation) ----------------
__device__ float g_f[Bsz*hh*ww*Cc];        // low-res image            2 MB
__device__ float g_m[Bsz*hh*ww];           // low-res mask
__device__ float g_rn[Bsz*Ll];             // 1/max(norm,1e-4)
__device__ float g_mm[Bsz*Ll];             // gate
__device__ float g_P[Bsz*Ll*KK];           // low-res patches (im2col) 18 MB
__device__ float g_R[Bsz*Ll*KK];           // raw patches              18 MB
__device__ float g_A[(size_t)Bsz*Ll*Ll];   // softmaxed attention     128 MB
__device__ float g_M[Bsz*Ll*KK];           // GEMM2 result             18 MB

// ---------------- stage 0: avgpool x->f, mask->m ----------------
__global__ void k_avgpool(const float* __restrict__ x, const float* __restrict__ mask) {
    int idx = blockIdx.x * blockDim.x + threadIdx.x;
    const int total = Bsz * hh * ww * Cc;
    if (idx < total) {
        int c = idx % Cc;
        int j = (idx / Cc) % ww;
        int i = (idx / (Cc * ww)) % hh;
        int b = idx / (Cc * ww * hh);
        const float* xb = x + (size_t)b * Hf * Wf * Cc;
        float s = xb[((2*i)   * Wf + 2*j  ) * Cc + c]
                + xb[((2*i)   * Wf + 2*j+1) * Cc + c]
                + xb[((2*i+1) * Wf + 2*j  ) * Cc + c]
                + xb[((2*i+1) * Wf + 2*j+1) * Cc + c];
        g_f[idx] = 0.25f * s;
    }
    if (idx < Bsz * hh * ww) {
        int j = idx % ww;
        int i = (idx / ww) % hh;
        int b = idx / (ww * hh);
        const float* mb = mask + (size_t)b * Hf * Wf;
        float s = mb[(2*i)*Wf + 2*j] + mb[(2*i)*Wf + 2*j+1]
                + mb[(2*i+1)*Wf + 2*j] + mb[(2*i+1)*Wf + 2*j+1];
        g_m[idx] = 0.25f * s;
    }
}

// ---------------- stage 1: im2col of f (3x3, stride 1, pad (1,1)) ----------------
__global__ void k_im2col_f() {
    int idx = blockIdx.x * blockDim.x + threadIdx.x;
    const int total = Bsz * Ll * KK;
    if (idx >= total) return;
    int kk = idx % KK;
    int p  = (idx / KK) % Ll;
    int b  = idx / (KK * Ll);
    int c  = kk % 64;
    int dw = (kk / 64) % 3;
    int dh = kk / 192;
    int i = p >> 6, j = p & 63;
    int ri = i - 1 + dh, rj = j - 1 + dw;
    float v = 0.f;
    if (ri >= 0 && ri < hh && rj >= 0 && rj < ww)
        v = g_f[(((size_t)b * hh + ri) * ww + rj) * Cc + c];
    g_P[idx] = v;
}

// ---------------- stage 2: im2col of raw x (3x3, stride 2, pad (0,1)) ----------------
__global__ void k_im2col_raw(const float* __restrict__ x) {
    int idx = blockIdx.x * blockDim.x + threadIdx.x;
    const int total = Bsz * Ll * KK;
    if (idx >= total) return;
    int kk = idx % KK;
    int p  = (idx / KK) % Ll;
    int b  = idx / (KK * Ll);
    int c  = kk % 64;
    int dw = (kk / 64) % 3;
    int dh = kk / 192;
    int i = p >> 6, j = p & 63;
    int ri = 2*i + dh, rj = 2*j + dw;   // pad only on bottom/right
    float v = 0.f;
    if (ri < Hf && rj < Wf)
        v = x[(((size_t)b * Hf + ri) * Wf + rj) * Cc + c];
    g_R[idx] = v;
}

// ---------------- stage 3: patch norms ----------------
__global__ void k_norm() {
    int gt = blockIdx.x * blockDim.x + threadIdx.x;
    int warp = gt >> 5;
    int lane = gt & 31;
    if (warp >= Bsz * Ll) return;
    const float* row = g_P + (size_t)warp * KK;
    float s = 0.f;
    for (int k = lane; k < KK; k += 32) { float v = row[k]; s += v * v; }
    #pragma unroll
    for (int o = 16; o > 0; o >>= 1) s += __shfl_xor_sync(0xffffffff, s, o);
    if (lane == 0) g_rn[warp] = 1.0f / fmaxf(sqrtf(s), 1e-4f);
}

// ---------------- stage 4: mask gate ----------------
__global__ void k_mmgate() {
    int idx = blockIdx.x * blockDim.x + threadIdx.x;
    if (idx >= Bsz * Ll) return;
    int q = idx % Ll;
    int b = idx / Ll;
    int i = q >> 6, j = q & 63;
    float s = 0.f;
    for (int dh = 0; dh < 3; dh++)
        for (int dw = 0; dw < 3; dw++) {
            int ri = i - 1 + dh, rj = j - 1 + dw;
            if (ri >= 0 && ri < hh && rj >= 0 && rj < ww)
                s += g_m[((size_t)b * hh + ri) * ww + rj];
        }
    g_mm[idx] = ((s / 9.0f) == 1.0f) ? 1.0f : 0.0f;
}

// ---------------- stage 5: GEMM1  att[p,q] = dot(P_p, P_q) * rn[q]  (symmetric) ----------------
__global__ __launch_bounds__(256) void k_gemm1(float* __restrict__ att) {
    int b  = blockIdx.z;
    int bi = blockIdx.y;   // p-tile
    int bj = blockIdx.x;   // q-tile
    if (bj < bi) return;   // exploit symmetry

    const float* A = g_P + (size_t)b * Ll * KK;
    float* Cmat = att + (size_t)b * ATT_PER_B;
    const float* rn = g_rn + b * Ll;

    __shared__ float As[16][128];
    __shared__ float Bs[16][128];

    int tid = threadIdx.x;
    int tx = tid & 15, ty = tid >> 4;
    int pBase = bi * 128, qBase = bj * 128;

    float acc[8][8];
    #pragma unroll
    for (int u = 0; u < 8; u++)
        #pragma unroll
        for (int v = 0; v < 8; v++) acc[u][v] = 0.f;

    int r  = tid >> 2;         // 0..63
    int kc = (tid & 3) * 4;    // 0,4,8,12

    for (int k0 = 0; k0 < KK; k0 += 16) {
        float4 a0 = *(const float4*)&A[(size_t)(pBase + r)      * KK + k0 + kc];
        float4 a1 = *(const float4*)&A[(size_t)(pBase + r + 64) * KK + k0 + kc];
        float4 b0 = *(const float4*)&A[(size_t)(qBase + r)      * KK + k0 + kc];
        float4 b1 = *(const float4*)&A[(size_t)(qBase + r + 64) * KK + k0 + kc];
        As[kc+0][r]    = a0.x; As[kc+1][r]    = a0.y; As[kc+2][r]    = a0.z; As[kc+3][r]    = a0.w;
        As[kc+0][r+64] = a1.x; As[kc+1][r+64] = a1.y; As[kc+2][r+64] = a1.z; As[kc+3][r+64] = a1.w;
        Bs[kc+0][r]    = b0.x; Bs[kc+1][r]    = b0.y; Bs[kc+2][r]    = b0.z; Bs[kc+3][r]    = b0.w;
        Bs[kc+0][r+64] = b1.x; Bs[kc+1][r+64] = b1.y; Bs[kc+2][r+64] = b1.z; Bs[kc+3][r+64] = b1.w;
        __syncthreads();
        #pragma unroll
        for (int k = 0; k < 16; k++) {
            float ar[8], br[8];
            #pragma unroll
            for (int u = 0; u < 8; u++) { ar[u] = As[k][ty*8 + u]; br[u] = Bs[k][tx*8 + u]; }
            #pragma unroll
            for (int u = 0; u < 8; u++)
                #pragma unroll
                for (int v = 0; v < 8; v++) acc[u][v] += ar[u] * br[v];
        }
        __syncthreads();
    }

    // epilogue: att[p,q] = acc * rn[q]
    float rq[8];
    #pragma unroll
    for (int v = 0; v < 8; v++) rq[v] = rn[qBase + tx*8 + v];
    #pragma unroll
    for (int u = 0; u < 8; u++) {
        size_t p = pBase + ty*8 + u;
        float4 w0 = make_float4(acc[u][0]*rq[0], acc[u][1]*rq[1], acc[u][2]*rq[2], acc[u][3]*rq[3]);
        float4 w1 = make_float4(acc[u][4]*rq[4], acc[u][5]*rq[5], acc[u][6]*rq[6], acc[u][7]*rq[7]);
        *(float4*)&Cmat[p * Ll + qBase + tx*8]     = w0;
        *(float4*)&Cmat[p * Ll + qBase + tx*8 + 4] = w1;
    }
    if (bi != bj) {
        float rp[8];
        #pragma unroll
        for (int u = 0; u < 8; u++) rp[u] = rn[pBase + ty*8 + u];
        #pragma unroll
        for (int v = 0; v < 8; v++) {
            size_t q = qBase + tx*8 + v;
            float4 w0 = make_float4(acc[0][v]*rp[0], acc[1][v]*rp[1], acc[2][v]*rp[2], acc[3][v]*rp[3]);
            float4 w1 = make_float4(acc[4][v]*rp[4], acc[5][v]*rp[5], acc[6][v]*rp[6], acc[7][v]*rp[7]);
            *(float4*)&Cmat[q * Ll + pBase + ty*8]     = w0;
            *(float4*)&Cmat[q * Ll + pBase + ty*8 + 4] = w1;
        }
    }
}

// ---------------- stage 6: fuse (two flattened diagonal convs) + softmax ----------------
__global__ __launch_bounds__(256) void k_fuse_softmax(const float* __restrict__ att) {
    int b = blockIdx.y;
    int p = blockIdx.x;                       // row index in F1 flattening (i*64+j)
    const float* Sb  = att + (size_t)b * ATT_PER_B;
    const float* mmb = g_mm + b * Ll;
    float* Arow = g_A + ((size_t)b * Ll + p) * Ll;

    __shared__ float zrow[Ll];
    __shared__ float red[256];

    int i = p >> 6, j = p & 63;
    int t = j * 64 + i;                       // F2 flattening

    int  Pb[3] = {0, 0, 0};
    bool pv[3];
    #pragma unroll
    for (int d = 0; d < 3; d++) {
        int tb = t + d - 1;
        pv[d] = (tb >= 0 && tb < Ll);
        if (pv[d]) Pb[d] = ((tb & 63) << 6) | (tb >> 6);   // back to F1
    }

    float lmax = -1e30f;
    for (int q = threadIdx.x; q < Ll; q += 256) {
        int u = ((q & 63) << 6) | (q >> 6);                // F2 of q
        float acc = 0.f;
        #pragma unroll
        for (int d = 0; d < 3; d++) {
            int ub = u + d - 1;
            if (pv[d] && ub >= 0 && ub < Ll) {
                int Q = ((ub & 63) << 6) | (ub >> 6);
                int P = Pb[d];
                #pragma unroll
                for (int a = -1; a <= 1; a++) {
                    int Pa = P + a, Qa = Q + a;
                    if (Pa >= 0 && Pa < Ll && Qa >= 0 && Qa < Ll)
                        acc += Sb[(size_t)Pa * Ll + Qa];
                }
            }
        }
        float val = acc * mmb[q] * 10.0f;
        zrow[q] = val;
        lmax = fmaxf(lmax, val);
    }
    red[threadIdx.x] = lmax;
    __syncthreads();
    for (int s = 128; s > 0; s >>= 1) {
        if (threadIdx.x < s) red[threadIdx.x] = fmaxf(red[threadIdx.x], red[threadIdx.x + s]);
        __syncthreads();
    }
    float mx = red[0];
    __syncthreads();

    float lsum = 0.f;
    for (int q = threadIdx.x; q < Ll; q += 256) {
        float e = __expf(zrow[q] - mx);
        zrow[q] = e;
        lsum += e;
    }
    red[threadIdx.x] = lsum;
    __syncthreads();
    for (int s = 128; s > 0; s >>= 1) {
        if (threadIdx.x < s) red[threadIdx.x] += red[threadIdx.x + s];
        __syncthreads();
    }
    float inv = 1.0f / red[0];
    for (int q = threadIdx.x; q < Ll; q += 256)
        Arow[q] = zrow[q] * inv * mmb[q];
}

// ---------------- stage 7: GEMM2  M = A[L,L] * R[L,576] ----------------
__global__ __launch_bounds__(256) void k_gemm2() {
    int b  = blockIdx.z;
    int bm = blockIdx.y;   // 0..31
    int bn = blockIdx.x;   // 0..8
    const float* A  = g_A + (size_t)b * Ll * Ll;
    const float* Bm = g_R + (size_t)b * Ll * KK;
    float* Cm = g_M + (size_t)b * Ll * KK;

    __shared__ float As[16][128];
    __shared__ float Bs[16][64];

    int tid = threadIdx.x;
    int tx = tid & 15, ty = tid >> 4;
    int mBase = bm * 128, nBase = bn * 64;

    float acc[8][4];
    #pragma unroll
    for (int u = 0; u < 8; u++)
        #pragma unroll
        for (int v = 0; v < 4; v++) acc[u][v] = 0.f;

    int r  = tid >> 2;
    int kc = (tid & 3) * 4;
    int br = tid >> 4;         // 0..15
    int bc = (tid & 15) * 4;   // 0..60

    for (int k0 = 0; k0 < Ll; k0 += 16) {
        float4 a0 = *(const float4*)&A[(size_t)(mBase + r)      * Ll + k0 + kc];
        float4 a1 = *(const float4*)&A[(size_t)(mBase + r + 64) * Ll + k0 + kc];
        As[kc+0][r]    = a0.x; As[kc+1][r]    = a0.y; As[kc+2][r]    = a0.z; As[kc+3][r]    = a0.w;
        As[kc+0][r+64] = a1.x; As[kc+1][r+64] = a1.y; As[kc+2][r+64] = a1.z; As[kc+3][r+64] = a1.w;
        *(float4*)&Bs[br][bc] = *(const float4*)&Bm[(size_t)(k0 + br) * KK + nBase + bc];
        __syncthreads();
        #pragma unroll
        for (int k = 0; k < 16; k++) {
            float ar[8], brg[4];
            #pragma unroll
            for (int u = 0; u < 8; u++) ar[u] = As[k][ty*8 + u];
            #pragma unroll
            for (int v = 0; v < 4; v++) brg[v] = Bs[k][tx*4 + v];
            #pragma unroll
            for (int u = 0; u < 8; u++)
                #pragma unroll
                for (int v = 0; v < 4; v++) acc[u][v] += ar[u] * brg[v];
        }
        __syncthreads();
    }
    #pragma unroll
    for (int u = 0; u < 8; u++) {
        float4 w = make_float4(acc[u][0], acc[u][1], acc[u][2], acc[u][3]);
        *(float4*)&Cm[(size_t)(mBase + ty*8 + u) * KK + nBase + tx*4] = w;
    }
}

// ---------------- stage 8: scatter (adjoint of stride-2 SAME conv), /4 ----------------
__global__ void k_scatter(float* __restrict__ y) {
    int idx = blockIdx.x * blockDim.x + threadIdx.x;   // over Bsz*Hf*Wf*16 (float4 over C)
    const int total = Bsz * Hf * Wf * (Cc / 4);
    if (idx >= total) return;
    int c4 = idx & 15;
    int qq = (idx >> 4) & 127;
    int pp = (idx >> 11) & 127;
    int b  = idx >> 18;

    const float* Mb = g_M + (size_t)b * Ll * KK;

    int icand[2], khc[2], nci = 0;
    if ((pp & 1) == 0) {
        icand[nci] = pp >> 1; khc[nci] = 0; nci++;
        if (pp >= 2) { icand[nci] = (pp >> 1) - 1; khc[nci] = 2; nci++; }
    } else { icand[0] = pp >> 1; khc[0] = 1; nci = 1; }

    int jcand[2], kwc[2], ncj = 0;
    if ((qq & 1) == 0) {
        jcand[ncj] = qq >> 1; kwc[ncj] = 0; ncj++;
        if (qq >= 2) { jcand[ncj] = (qq >> 1) - 1; kwc[ncj] = 2; ncj++; }
    } else { jcand[0] = qq >> 1; kwc[0] = 1; ncj = 1; }

    float4 s = make_float4(0.f, 0.f, 0.f, 0.f);
    for (int a = 0; a < nci; a++)
        for (int c = 0; c < ncj; c++) {
            const float4 v = *(const float4*)&Mb[(size_t)(icand[a] * 64 + jcand[c]) * KK
                                                 + (khc[a] * 3 + kwc[c]) * 64 + c4 * 4];
            s.x += v.x; s.y += v.y; s.z += v.z; s.w += v.w;
        }
    s.x *= 0.25f; s.y *= 0.25f; s.z *= 0.25f; s.w *= 0.25f;
    ((float4*)y)[idx] = s;
}

// ---------------- launch ----------------
extern "C" void kernel_launch(void* const* d_in, const int* in_sizes, int n_in,
                              void* d_out, int out_size) {
    const float* x    = (const float*)d_in[0];
    const float* mask = (const float*)d_in[1];
    float* out = (float*)d_out;
    float* y   = out;                 // [2,128,128,64]
    float* att = out + Y_ELEMS;       // [2,64,64,4096]

    k_avgpool   <<<(Bsz*hh*ww*Cc + 255) / 256, 256>>>(x, mask);
    k_im2col_f  <<<(Bsz*Ll*KK + 255) / 256, 256>>>();
    k_im2col_raw<<<(Bsz*Ll*KK + 255) / 256, 256>>>(x);
    k_norm      <<<(Bsz*Ll*32 + 255) / 256, 256>>>();
    k_mmgate    <<<(Bsz*Ll + 255) / 256, 256>>>();
    k_gemm1     <<<dim3(32, 32, Bsz), 256>>>(att);
    k_fuse_softmax<<<dim3(Ll, Bsz), 256>>>(att);
    k_gemm2     <<<dim3(9, 32, Bsz), 256>>>();
    k_scatter   <<<(Bsz*Hf*Wf*16 + 255) / 256, 256>>>(y);
}

// round 2
// speedup vs baseline: 2.0071x; 2.0071x over previous
#include <cuda_runtime.h>

// ---------------- problem constants ----------------
#define Bsz 2
#define Hf 128
#define Wf 128
#define Cc 64
#define hh 64
#define ww 64
#define Ll 4096          // hh*ww
#define KK 576           // 3*3*64
#define Y_ELEMS (Bsz*Hf*Wf*Cc)        // 2097152
#define ATT_PER_B ((size_t)Ll*Ll)     // 16777216

// ---------------- scratch (static device globals; no allocation) ----------------
__device__ float g_f[Bsz*hh*ww*Cc];        // low-res image
__device__ float g_m[Bsz*hh*ww];           // low-res mask
__device__ float g_rn[Bsz*Ll];             // 1/max(norm,1e-4)
__device__ float g_mm[Bsz*Ll];             // gate
__device__ int   g_cnt[Bsz];               // # gated columns
__device__ int   g_idxl[Bsz*Ll];           // compacted gated column indices
__device__ float g_P[Bsz*Ll*KK];           // low-res patches (im2col)
__device__ float g_R[Bsz*Ll*KK];           // raw patches
__device__ float g_A[(size_t)Bsz*Ll*Ll];   // softmaxed attention (compacted cols)
__device__ float g_M[Bsz*Ll*KK];           // GEMM2 result

// ---------------- stage 0: avgpool x->f, mask->m ----------------
__global__ void k_avgpool(const float* __restrict__ x, const float* __restrict__ mask) {
    int idx = blockIdx.x * blockDim.x + threadIdx.x;
    const int total = Bsz * hh * ww * Cc;
    if (idx < total) {
        int c = idx % Cc;
        int j = (idx / Cc) % ww;
        int i = (idx / (Cc * ww)) % hh;
        int b = idx / (Cc * ww * hh);
        const float* xb = x + (size_t)b * Hf * Wf * Cc;
        float s = xb[((2*i)   * Wf + 2*j  ) * Cc + c]
                + xb[((2*i)   * Wf + 2*j+1) * Cc + c]
                + xb[((2*i+1) * Wf + 2*j  ) * Cc + c]
                + xb[((2*i+1) * Wf + 2*j+1) * Cc + c];
        g_f[idx] = 0.25f * s;
    }
    if (idx < Bsz * hh * ww) {
        int j = idx % ww;
        int i = (idx / ww) % hh;
        int b = idx / (ww * hh);
        const float* mb = mask + (size_t)b * Hf * Wf;
        float s = mb[(2*i)*Wf + 2*j] + mb[(2*i)*Wf + 2*j+1]
                + mb[(2*i+1)*Wf + 2*j] + mb[(2*i+1)*Wf + 2*j+1];
        g_m[idx] = 0.25f * s;
    }
}

// ---------------- stage 1: im2col of f (3x3, stride 1, pad (1,1)) ----------------
__global__ void k_im2col_f() {
    int idx = blockIdx.x * blockDim.x + threadIdx.x;
    const int total = Bsz * Ll * KK;
    if (idx >= total) return;
    int kk = idx % KK;
    int p  = (idx / KK) % Ll;
    int b  = idx / (KK * Ll);
    int c  = kk % 64;
    int dw = (kk / 64) % 3;
    int dh = kk / 192;
    int i = p >> 6, j = p & 63;
    int ri = i - 1 + dh, rj = j - 1 + dw;
    float v = 0.f;
    if (ri >= 0 && ri < hh && rj >= 0 && rj < ww)
        v = g_f[(((size_t)b * hh + ri) * ww + rj) * Cc + c];
    g_P[idx] = v;
}

// ---------------- stage 2: im2col of raw x (3x3, stride 2, pad (0,1)) ----------------
__global__ void k_im2col_raw(const float* __restrict__ x) {
    int idx = blockIdx.x * blockDim.x + threadIdx.x;
    const int total = Bsz * Ll * KK;
    if (idx >= total) return;
    int kk = idx % KK;
    int p  = (idx / KK) % Ll;
    int b  = idx / (KK * Ll);
    int c  = kk % 64;
    int dw = (kk / 64) % 3;
    int dh = kk / 192;
    int i = p >> 6, j = p & 63;
    int ri = 2*i + dh, rj = 2*j + dw;   // pad only on bottom/right
    float v = 0.f;
    if (ri < Hf && rj < Wf)
        v = x[(((size_t)b * Hf + ri) * Wf + rj) * Cc + c];
    g_R[idx] = v;
}

// ---------------- stage 3: patch norms ----------------
__global__ void k_norm() {
    int gt = blockIdx.x * blockDim.x + threadIdx.x;
    int warp = gt >> 5;
    int lane = gt & 31;
    if (warp >= Bsz * Ll) return;
    const float* row = g_P + (size_t)warp * KK;
    float s = 0.f;
    for (int k = lane; k < KK; k += 32) { float v = row[k]; s += v * v; }
    #pragma unroll
    for (int o = 16; o > 0; o >>= 1) s += __shfl_xor_sync(0xffffffff, s, o);
    if (lane == 0) g_rn[warp] = 1.0f / fmaxf(sqrtf(s), 1e-4f);
}

// ---------------- stage 4: mask gate ----------------
__global__ void k_mmgate() {
    int idx = blockIdx.x * blockDim.x + threadIdx.x;
    if (idx >= Bsz * Ll) return;
    int q = idx % Ll;
    int b = idx / Ll;
    int i = q >> 6, j = q & 63;
    float s = 0.f;
    for (int dh = 0; dh < 3; dh++)
        for (int dw = 0; dw < 3; dw++) {
            int ri = i - 1 + dh, rj = j - 1 + dw;
            if (ri >= 0 && ri < hh && rj >= 0 && rj < ww)
                s += g_m[((size_t)b * hh + ri) * ww + rj];
        }
    g_mm[idx] = ((s / 9.0f) == 1.0f) ? 1.0f : 0.0f;
}

// ---------------- stage 4b: compact gated columns (order-preserving) ----------------
__global__ __launch_bounds__(256) void k_compact() {
    int b = blockIdx.x;
    __shared__ int cnts[256];
    __shared__ int offs[257];
    int t = threadIdx.x;
    const float* mmb = g_mm + b * Ll;
    int base = t * 16;
    int local = 0;
    #pragma unroll
    for (int e = 0; e < 16; e++) local += (mmb[base + e] != 0.f) ? 1 : 0;
    cnts[t] = local;
    __syncthreads();
    if (t == 0) {
        int run = 0;
        for (int s = 0; s < 256; s++) { offs[s] = run; run += cnts[s]; }
        offs[256] = run;
        g_cnt[b] = run;
    }
    __syncthreads();
    int o = offs[t];
    int* idxb = g_idxl + b * Ll;
    #pragma unroll
    for (int e = 0; e < 16; e++)
        if (mmb[base + e] != 0.f) idxb[o++] = base + e;
}

// ---------------- stage 5: GEMM1  att[p,q] = dot(P_p, P_q) * rn[q]  (symmetric) ----------------
__global__ __launch_bounds__(256) void k_gemm1(float* __restrict__ att) {
    int b  = blockIdx.z;
    int bi = blockIdx.y;   // p-tile
    int bj = blockIdx.x;   // q-tile
    if (bj < bi) return;   // exploit symmetry

    const float* A = g_P + (size_t)b * Ll * KK;
    float* Cmat = att + (size_t)b * ATT_PER_B;
    const float* rn = g_rn + b * Ll;

    __shared__ float As[16][128];
    __shared__ float Bs[16][128];

    int tid = threadIdx.x;
    int tx = tid & 15, ty = tid >> 4;
    int pBase = bi * 128, qBase = bj * 128;

    float acc[8][8];
    #pragma unroll
    for (int u = 0; u < 8; u++)
        #pragma unroll
        for (int v = 0; v < 8; v++) acc[u][v] = 0.f;

    int r  = tid >> 2;         // 0..63
    int kc = (tid & 3) * 4;    // 0,4,8,12

    for (int k0 = 0; k0 < KK; k0 += 16) {
        float4 a0 = *(const float4*)&A[(size_t)(pBase + r)      * KK + k0 + kc];
        float4 a1 = *(const float4*)&A[(size_t)(pBase + r + 64) * KK + k0 + kc];
        float4 b0 = *(const float4*)&A[(size_t)(qBase + r)      * KK + k0 + kc];
        float4 b1 = *(const float4*)&A[(size_t)(qBase + r + 64) * KK + k0 + kc];
        As[kc+0][r]    = a0.x; As[kc+1][r]    = a0.y; As[kc+2][r]    = a0.z; As[kc+3][r]    = a0.w;
        As[kc+0][r+64] = a1.x; As[kc+1][r+64] = a1.y; As[kc+2][r+64] = a1.z; As[kc+3][r+64] = a1.w;
        Bs[kc+0][r]    = b0.x; Bs[kc+1][r]    = b0.y; Bs[kc+2][r]    = b0.z; Bs[kc+3][r]    = b0.w;
        Bs[kc+0][r+64] = b1.x; Bs[kc+1][r+64] = b1.y; Bs[kc+2][r+64] = b1.z; Bs[kc+3][r+64] = b1.w;
        __syncthreads();
        #pragma unroll
        for (int k = 0; k < 16; k++) {
            float4 ar0 = *(const float4*)&As[k][ty*8];
            float4 ar1 = *(const float4*)&As[k][ty*8 + 4];
            float4 br0 = *(const float4*)&Bs[k][tx*8];
            float4 br1 = *(const float4*)&Bs[k][tx*8 + 4];
            float ar[8] = {ar0.x, ar0.y, ar0.z, ar0.w, ar1.x, ar1.y, ar1.z, ar1.w};
            float br[8] = {br0.x, br0.y, br0.z, br0.w, br1.x, br1.y, br1.z, br1.w};
            #pragma unroll
            for (int u = 0; u < 8; u++)
                #pragma unroll
                for (int v = 0; v < 8; v++) acc[u][v] += ar[u] * br[v];
        }
        __syncthreads();
    }

    // epilogue: att[p,q] = acc * rn[q]
    float rq[8];
    #pragma unroll
    for (int v = 0; v < 8; v++) rq[v] = rn[qBase + tx*8 + v];
    #pragma unroll
    for (int u = 0; u < 8; u++) {
        size_t p = pBase + ty*8 + u;
        float4 w0 = make_float4(acc[u][0]*rq[0], acc[u][1]*rq[1], acc[u][2]*rq[2], acc[u][3]*rq[3]);
        float4 w1 = make_float4(acc[u][4]*rq[4], acc[u][5]*rq[5], acc[u][6]*rq[6], acc[u][7]*rq[7]);
        *(float4*)&Cmat[p * Ll + qBase + tx*8]     = w0;
        *(float4*)&Cmat[p * Ll + qBase + tx*8 + 4] = w1;
    }
    if (bi != bj) {
        float rp[8];
        #pragma unroll
        for (int u = 0; u < 8; u++) rp[u] = rn[pBase + ty*8 + u];
        #pragma unroll
        for (int v = 0; v < 8; v++) {
            size_t q = qBase + tx*8 + v;
            float4 w0 = make_float4(acc[0][v]*rp[0], acc[1][v]*rp[1], acc[2][v]*rp[2], acc[3][v]*rp[3]);
            float4 w1 = make_float4(acc[4][v]*rp[4], acc[5][v]*rp[5], acc[6][v]*rp[6], acc[7][v]*rp[7]);
            *(float4*)&Cmat[q * Ll + pBase + ty*8]     = w0;
            *(float4*)&Cmat[q * Ll + pBase + ty*8 + 4] = w1;
        }
    }
}

// ---------------- stage 6: fuse + softmax over gated columns only ----------------
// Ungated columns have logit exactly 0 (val = acc*mm*10 with mm=0); they contribute
// (Ll-cnt)*exp(-max) to the denominator and 0 to the output. Output stored compacted:
// g_A[p][k] = A[p][idx[k]].
__global__ __launch_bounds__(256) void k_fuse_softmax(const float* __restrict__ att) {
    int b = blockIdx.y;
    int p = blockIdx.x;                       // row index in F1 flattening (i*64+j)
    const float* Sb  = att + (size_t)b * ATT_PER_B;
    int cnt = g_cnt[b];
    const int* idxb = g_idxl + b * Ll;
    float* Arow = g_A + ((size_t)b * Ll + p) * Ll;

    __shared__ float zrow[Ll];
    __shared__ float red[256];

    int i = p >> 6, j = p & 63;
    int t = j * 64 + i;                       // F2 flattening

    int  Pb[3] = {0, 0, 0};
    bool pv[3];
    #pragma unroll
    for (int d = 0; d < 3; d++) {
        int tb = t + d - 1;
        pv[d] = (tb >= 0 && tb < Ll);
        if (pv[d]) Pb[d] = ((tb & 63) << 6) | (tb >> 6);   // back to F1
    }

    float lmax = (cnt < Ll) ? 0.0f : -3.4e38f;   // ungated entries have logit 0
    for (int k = threadIdx.x; k < cnt; k += 256) {
        int q = idxb[k];
        int u = ((q & 63) << 6) | (q >> 6);                // F2 of q
        float acc = 0.f;
        #pragma unroll
        for (int d = 0; d < 3; d++) {
            int ub = u + d - 1;
            if (pv[d] && ub >= 0 && ub < Ll) {
                int Q = ((ub & 63) << 6) | (ub >> 6);
                int P = Pb[d];
                #pragma unroll
                for (int a = -1; a <= 1; a++) {
                    int Pa = P + a, Qa = Q + a;
                    if (Pa >= 0 && Pa < Ll && Qa >= 0 && Qa < Ll)
                        acc += Sb[(size_t)Pa * Ll + Qa];
                }
            }
        }
        float val = acc * 10.0f;              // mm == 1 for gated columns
        zrow[k] = val;
        lmax = fmaxf(lmax, val);
    }
    red[threadIdx.x] = lmax;
    __syncthreads();
    for (int s = 128; s > 0; s >>= 1) {
        if (threadIdx.x < s) red[threadIdx.x] = fmaxf(red[threadIdx.x], red[threadIdx.x + s]);
        __syncthreads();
    }
    float mx = red[0];
    __syncthreads();

    float lsum = 0.f;
    for (int k = threadIdx.x; k < cnt; k += 256) {
        float e = __expf(zrow[k] - mx);
        zrow[k] = e;
        lsum += e;
    }
    red[threadIdx.x] = lsum;
    __syncthreads();
    for (int s = 128; s > 0; s >>= 1) {
        if (threadIdx.x < s) red[threadIdx.x] += red[threadIdx.x + s];
        __syncthreads();
    }
    float denom = red[0] + (float)(Ll - cnt) * __expf(-mx);
    float inv = 1.0f / denom;
    for (int k = threadIdx.x; k < cnt; k += 256)
        Arow[k] = zrow[k] * inv;
    // zero-pad to next multiple of 16 for GEMM2's K-tiling
    int kpad = (cnt + 15) & ~15;
    for (int k = cnt + (int)threadIdx.x; k < kpad; k += 256)
        Arow[k] = 0.f;
}

// ---------------- stage 7: GEMM2  M[L,576] = A_compact[L,cnt] * R[idx[cnt],576] ----------------
__global__ __launch_bounds__(256) void k_gemm2() {
    int b  = blockIdx.z;
    int bm = blockIdx.y;   // 0..31
    int bn = blockIdx.x;   // 0..8
    const float* A  = g_A + (size_t)b * Ll * Ll;
    const float* Bm = g_R + (size_t)b * Ll * KK;
    float* Cm = g_M + (size_t)b * Ll * KK;
    int cnt = g_cnt[b];
    int kpad = (cnt + 15) & ~15;
    const int* idxb = g_idxl + b * Ll;

    __shared__ float As[16][128];
    __shared__ float Bs[16][64];

    int tid = threadIdx.x;
    int tx = tid & 15, ty = tid >> 4;
    int mBase = bm * 128, nBase = bn * 64;

    float acc[8][4];
    #pragma unroll
    for (int u = 0; u < 8; u++)
        #pragma unroll
        for (int v = 0; v < 4; v++) acc[u][v] = 0.f;

    int r  = tid >> 2;
    int kc = (tid & 3) * 4;
    int br = tid >> 4;         // 0..15
    int bc = (tid & 15) * 4;   // 0..60

    for (int k0 = 0; k0 < kpad; k0 += 16) {
        float4 a0 = *(const float4*)&A[(size_t)(mBase + r)      * Ll + k0 + kc];
        float4 a1 = *(const float4*)&A[(size_t)(mBase + r + 64) * Ll + k0 + kc];
        As[kc+0][r]    = a0.x; As[kc+1][r]    = a0.y; As[kc+2][r]    = a0.z; As[kc+3][r]    = a0.w;
        As[kc+0][r+64] = a1.x; As[kc+1][r+64] = a1.y; As[kc+2][r+64] = a1.z; As[kc+3][r+64] = a1.w;
        int kg = k0 + br;
        float4 bv = make_float4(0.f, 0.f, 0.f, 0.f);
        if (kg < cnt)
            bv = *(const float4*)&Bm[(size_t)idxb[kg] * KK + nBase + bc];
        *(float4*)&Bs[br][bc] = bv;
        __syncthreads();
        #pragma unroll
        for (int k = 0; k < 16; k++) {
            float4 ar0 = *(const float4*)&As[k][ty*8];
            float4 ar1 = *(const float4*)&As[k][ty*8 + 4];
            float4 brv = *(const float4*)&Bs[k][tx*4];
            float ar[8] = {ar0.x, ar0.y, ar0.z, ar0.w, ar1.x, ar1.y, ar1.z, ar1.w};
            float brg[4] = {brv.x, brv.y, brv.z, brv.w};
            #pragma unroll
            for (int u = 0; u < 8; u++)
                #pragma unroll
                for (int v = 0; v < 4; v++) acc[u][v] += ar[u] * brg[v];
        }
        __syncthreads();
    }
    #pragma unroll
    for (int u = 0; u < 8; u++) {
        float4 w = make_float4(acc[u][0], acc[u][1], acc[u][2], acc[u][3]);
        *(float4*)&Cm[(size_t)(mBase + ty*8 + u) * KK + nBase + tx*4] = w;
    }
}

// ---------------- stage 8: scatter (adjoint of stride-2 SAME conv), /4 ----------------
__global__ void k_scatter(float* __restrict__ y) {
    int idx = blockIdx.x * blockDim.x + threadIdx.x;   // over Bsz*Hf*Wf*16 (float4 over C)
    const int total = Bsz * Hf * Wf * (Cc / 4);
    if (idx >= total) return;
    int c4 = idx & 15;
    int qq = (idx >> 4) & 127;
    int pp = (idx >> 11) & 127;
    int b  = idx >> 18;

    const float* Mb = g_M + (size_t)b * Ll * KK;

    int icand[2], khc[2], nci = 0;
    if ((pp & 1) == 0) {
        icand[nci] = pp >> 1; khc[nci] = 0; nci++;
        if (pp >= 2) { icand[nci] = (pp >> 1) - 1; khc[nci] = 2; nci++; }
    } else { icand[0] = pp >> 1; khc[0] = 1; nci = 1; }

    int jcand[2], kwc[2], ncj = 0;
    if ((qq & 1) == 0) {
        jcand[ncj] = qq >> 1; kwc[ncj] = 0; ncj++;
        if (qq >= 2) { jcand[ncj] = (qq >> 1) - 1; kwc[ncj] = 2; ncj++; }
    } else { jcand[0] = qq >> 1; kwc[0] = 1; ncj = 1; }

    float4 s = make_float4(0.f, 0.f, 0.f, 0.f);
    for (int a = 0; a < nci; a++)
        for (int c = 0; c < ncj; c++) {
            const float4 v = *(const float4*)&Mb[(size_t)(icand[a] * 64 + jcand[c]) * KK
                                                 + (khc[a] * 3 + kwc[c]) * 64 + c4 * 4];
            s.x += v.x; s.y += v.y; s.z += v.z; s.w += v.w;
        }
    s.x *= 0.25f; s.y *= 0.25f; s.z *= 0.25f; s.w *= 0.25f;
    ((float4*)y)[idx] = s;
}

// ---------------- launch ----------------
extern "C" void kernel_launch(void* const* d_in, const int* in_sizes, int n_in,
                              void* d_out, int out_size) {
    const float* x    = (const float*)d_in[0];
    const float* mask = (const float*)d_in[1];
    float* out = (float*)d_out;
    float* y   = out;                 // [2,128,128,64]
    float* att = out + Y_ELEMS;       // [2,64,64,4096]

    k_avgpool   <<<(Bsz*hh*ww*Cc + 255) / 256, 256>>>(x, mask);
    k_im2col_f  <<<(Bsz*Ll*KK + 255) / 256, 256>>>();
    k_im2col_raw<<<(Bsz*Ll*KK + 255) / 256, 256>>>(x);
    k_norm      <<<(Bsz*Ll*32 + 255) / 256, 256>>>();
    k_mmgate    <<<(Bsz*Ll + 255) / 256, 256>>>();
    k_compact   <<<Bsz, 256>>>();
    k_gemm1     <<<dim3(32, 32, Bsz), 256>>>(att);
    k_fuse_softmax<<<dim3(Ll, Bsz), 256>>>(att);
    k_gemm2     <<<dim3(9, 32, Bsz), 256>>>();
    k_scatter   <<<(Bsz*Hf*Wf*16 + 255) / 256, 256>>>(y);
}

// round 4
// speedup vs baseline: 3.1240x; 1.5564x over previous
#include <cuda_runtime.h>
#include <cuda_bf16.h>
#include <cstdint>

// ---------------- problem constants ----------------
#define Bsz 2
#define Hf 128
#define Wf 128
#define Cc 64
#define hh 64
#define ww 64
#define Ll 4096          // hh*ww
#define KK 576           // 3*3*64
#define Y_ELEMS (Bsz*Hf*Wf*Cc)        // 2097152
#define ATT_PER_B ((size_t)Ll*Ll)     // 16777216

// ---------------- scratch (static device globals; no allocation) ----------------
__device__ float g_f[Bsz*hh*ww*Cc];        // low-res image
__device__ float g_m[Bsz*hh*ww];           // low-res mask
__device__ float g_rn[Bsz*Ll];             // 1/max(norm,1e-4)
__device__ float g_mm[Bsz*Ll];             // gate
__device__ int   g_cnt[Bsz];               // # gated columns
__device__ int   g_idxl[Bsz*Ll];           // compacted gated column indices
__device__ __align__(256) __nv_bfloat16 g_Phi[Bsz*Ll*KK]; // patches, bf16 hi
__device__ __align__(256) __nv_bfloat16 g_Plo[Bsz*Ll*KK]; // patches, bf16 lo (residual)
__device__ float g_R[Bsz*Ll*KK];           // raw patches
__device__ float g_A[(size_t)Bsz*Ll*Ll];   // softmaxed attention (compacted cols)
__device__ float g_M[Bsz*Ll*KK];           // GEMM2 result

// ---------------- warp-mma helpers (baseline PTX, no 'a' features) ----------------
__device__ __forceinline__ uint32_t smem_u32(const void* p) {
    uint32_t a;
    asm("{ .reg .u64 t; cvta.to.shared.u64 t, %1; cvt.u32.u64 %0, t; }" : "=r"(a) : "l"(p));
    return a;
}
__device__ __forceinline__ void ldsm_x4(uint32_t& r0, uint32_t& r1, uint32_t& r2, uint32_t& r3,
                                        uint32_t addr) {
    asm volatile("ldmatrix.sync.aligned.m8n8.x4.shared.b16 {%0,%1,%2,%3}, [%4];"
                 : "=r"(r0), "=r"(r1), "=r"(r2), "=r"(r3) : "r"(addr));
}
__device__ __forceinline__ void mma_bf16(float* d, const uint32_t* a, uint32_t b0, uint32_t b1) {
    asm volatile(
        "mma.sync.aligned.m16n8k16.row.col.f32.bf16.bf16.f32 "
        "{%0,%1,%2,%3}, {%4,%5,%6,%7}, {%8,%9}, {%0,%1,%2,%3};"
        : "+f"(d[0]), "+f"(d[1]), "+f"(d[2]), "+f"(d[3])
        : "r"(a[0]), "r"(a[1]), "r"(a[2]), "r"(a[3]), "r"(b0), "r"(b1));
}

// ---------------- stage 0: avgpool x->f, mask->m ----------------
__global__ void k_avgpool(const float* __restrict__ x, const float* __restrict__ mask) {
    int idx = blockIdx.x * blockDim.x + threadIdx.x;
    const int total = Bsz * hh * ww * Cc;
    if (idx < total) {
        int c = idx % Cc;
        int j = (idx / Cc) % ww;
        int i = (idx / (Cc * ww)) % hh;
        int b = idx / (Cc * ww * hh);
        const float* xb = x + (size_t)b * Hf * Wf * Cc;
        float s = xb[((2*i)   * Wf + 2*j  ) * Cc + c]
                + xb[((2*i)   * Wf + 2*j+1) * Cc + c]
                + xb[((2*i+1) * Wf + 2*j  ) * Cc + c]
                + xb[((2*i+1) * Wf + 2*j+1) * Cc + c];
        g_f[idx] = 0.25f * s;
    }
    if (idx < Bsz * hh * ww) {
        int j = idx % ww;
        int i = (idx / ww) % hh;
        int b = idx / (ww * hh);
        const float* mb = mask + (size_t)b * Hf * Wf;
        float s = mb[(2*i)*Wf + 2*j] + mb[(2*i)*Wf + 2*j+1]
                + mb[(2*i+1)*Wf + 2*j] + mb[(2*i+1)*Wf + 2*j+1];
        g_m[idx] = 0.25f * s;
    }
}

// ---------------- stage 1: im2col of f -> bf16 hi/lo split ----------------
__global__ void k_im2col_f() {
    int idx = blockIdx.x * blockDim.x + threadIdx.x;
    const int total = Bsz * Ll * KK;
    if (idx >= total) return;
    int kk = idx % KK;
    int p  = (idx / KK) % Ll;
    int b  = idx / (KK * Ll);
    int c  = kk % 64;
    int dw = (kk / 64) % 3;
    int dh = kk / 192;
    int i = p >> 6, j = p & 63;
    int ri = i - 1 + dh, rj = j - 1 + dw;
    float v = 0.f;
    if (ri >= 0 && ri < hh && rj >= 0 && rj < ww)
        v = g_f[(((size_t)b * hh + ri) * ww + rj) * Cc + c];
    __nv_bfloat16 hv = __float2bfloat16(v);
    g_Phi[idx] = hv;
    g_Plo[idx] = __float2bfloat16(v - __bfloat162float(hv));
}

// ---------------- stage 2: im2col of raw x (3x3, stride 2, pad (0,1)) ----------------
__global__ void k_im2col_raw(const float* __restrict__ x) {
    int idx = blockIdx.x * blockDim.x + threadIdx.x;
    const int total = Bsz * Ll * KK;
    if (idx >= total) return;
    int kk = idx % KK;
    int p  = (idx / KK) % Ll;
    int b  = idx / (KK * Ll);
    int c  = kk % 64;
    int dw = (kk / 64) % 3;
    int dh = kk / 192;
    int i = p >> 6, j = p & 63;
    int ri = 2*i + dh, rj = 2*j + dw;   // pad only on bottom/right
    float v = 0.f;
    if (ri < Hf && rj < Wf)
        v = x[(((size_t)b * Hf + ri) * Wf + rj) * Cc + c];
    g_R[idx] = v;
}

// ---------------- stage 3: patch norms (from hi+lo) ----------------
__global__ void k_norm() {
    int gt = blockIdx.x * blockDim.x + threadIdx.x;
    int warp = gt >> 5;
    int lane = gt & 31;
    if (warp >= Bsz * Ll) return;
    const __nv_bfloat16* rh = g_Phi + (size_t)warp * KK;
    const __nv_bfloat16* rl = g_Plo + (size_t)warp * KK;
    float s = 0.f;
    for (int k = lane; k < KK; k += 32) {
        float v = __bfloat162float(rh[k]) + __bfloat162float(rl[k]);
        s += v * v;
    }
    #pragma unroll
    for (int o = 16; o > 0; o >>= 1) s += __shfl_xor_sync(0xffffffff, s, o);
    if (lane == 0) g_rn[warp] = 1.0f / fmaxf(sqrtf(s), 1e-4f);
}

// ---------------- stage 4: mask gate ----------------
__global__ void k_mmgate() {
    int idx = blockIdx.x * blockDim.x + threadIdx.x;
    if (idx >= Bsz * Ll) return;
    int q = idx % Ll;
    int b = idx / Ll;
    int i = q >> 6, j = q & 63;
    float s = 0.f;
    for (int dh = 0; dh < 3; dh++)
        for (int dw = 0; dw < 3; dw++) {
            int ri = i - 1 + dh, rj = j - 1 + dw;
            if (ri >= 0 && ri < hh && rj >= 0 && rj < ww)
                s += g_m[((size_t)b * hh + ri) * ww + rj];
        }
    g_mm[idx] = ((s / 9.0f) == 1.0f) ? 1.0f : 0.0f;
}

// ---------------- stage 4b: compact gated columns ----------------
__global__ __launch_bounds__(256) void k_compact() {
    int b = blockIdx.x;
    __shared__ int cnts[256];
    __shared__ int offs[257];
    int t = threadIdx.x;
    const float* mmb = g_mm + b * Ll;
    int base = t * 16;
    int local = 0;
    #pragma unroll
    for (int e = 0; e < 16; e++) local += (mmb[base + e] != 0.f) ? 1 : 0;
    cnts[t] = local;
    __syncthreads();
    if (t == 0) {
        int run = 0;
        for (int s = 0; s < 256; s++) { offs[s] = run; run += cnts[s]; }
        offs[256] = run;
        g_cnt[b] = run;
    }
    __syncthreads();
    int o = offs[t];
    int* idxb = g_idxl + b * Ll;
    #pragma unroll
    for (int e = 0; e < 16; e++)
        if (mmb[base + e] != 0.f) idxb[o++] = base + e;
}

// ---------------- stage 5: GEMM1 via mma.sync bf16 hi/lo (symmetric syrk) ----------------
// smem: sAhi/sAlo/sBhi/sBlo, each 128 rows x PITCH(72) bf16; epilogue reuses as C[128][129] f32.
#define PITCH 72
#define ARR_B (128 * PITCH * 2)       // 18432 bytes
#define G1_SMEM (4 * ARR_B)           // 73728 bytes
__global__ __launch_bounds__(256, 1) void k_gemm1_mma(float* __restrict__ att) {
    int b  = blockIdx.z;
    int bi = blockIdx.y;
    int bj = blockIdx.x;
    if (bj < bi) return;

    extern __shared__ char sm[];
    __nv_bfloat16* sAhi = (__nv_bfloat16*)(sm);
    __nv_bfloat16* sAlo = (__nv_bfloat16*)(sm + ARR_B);
    __nv_bfloat16* sBhi = (__nv_bfloat16*)(sm + 2 * ARR_B);
    __nv_bfloat16* sBlo = (__nv_bfloat16*)(sm + 3 * ARR_B);
    uint32_t uAhi = smem_u32(sAhi), uAlo = smem_u32(sAlo);
    uint32_t uBhi = smem_u32(sBhi), uBlo = smem_u32(sBlo);

    int tid = threadIdx.x;
    int wid = tid >> 5;
    int lane = tid & 31;
    int mw = wid >> 2;       // 0..1
    int nw = wid & 3;        // 0..3

    const __nv_bfloat16* Phi = g_Phi + (size_t)b * Ll * KK;
    const __nv_bfloat16* Plo = g_Plo + (size_t)b * Ll * KK;
    int pBase = bi * 128, qBase = bj * 128;

    float d[4][4][4];
    #pragma unroll
    for (int mi = 0; mi < 4; mi++)
        #pragma unroll
        for (int ni = 0; ni < 4; ni++)
            #pragma unroll
            for (int e = 0; e < 4; e++) d[mi][ni][e] = 0.f;

    // precompute ldmatrix lane addresses (byte offsets within each array)
    int aRow = lane & 15;
    int aKof = ((lane >> 4) & 1) * 8;
    int bGrp = lane >> 3;
    int bLr  = lane & 7;
    int bNt  = bGrp >> 1;             // 0,0,1,1
    int bKof = (bGrp & 1) * 8;

    #pragma unroll 1
    for (int ch = 0; ch < 9; ch++) {
        int k0 = ch * 64;
        // load chunk: 4 arrays x 128 rows x 64 bf16 (8 uint4 per row)
        #pragma unroll
        for (int it = 0; it < 4; it++) {
            int idx = it * 256 + tid;
            int row = idx >> 3;
            int c4  = idx & 7;
            size_t goffA = (size_t)(pBase + row) * KK + k0 + c4 * 8;
            size_t goffB = (size_t)(qBase + row) * KK + k0 + c4 * 8;
            int soff = row * PITCH + c4 * 8;
            *(uint4*)&sAhi[soff] = *(const uint4*)&Phi[goffA];
            *(uint4*)&sAlo[soff] = *(const uint4*)&Plo[goffA];
            *(uint4*)&sBhi[soff] = *(const uint4*)&Phi[goffB];
            *(uint4*)&sBlo[soff] = *(const uint4*)&Plo[goffB];
        }
        __syncthreads();

        #pragma unroll
        for (int ks = 0; ks < 4; ks++) {
            uint32_t ah[4][4], al[4][4], bhr[2][4], blr[2][4];
            #pragma unroll
            for (int mi = 0; mi < 4; mi++) {
                uint32_t off = ((mw * 64 + mi * 16 + aRow) * PITCH + ks * 16 + aKof) * 2;
                ldsm_x4(ah[mi][0], ah[mi][1], ah[mi][2], ah[mi][3], uAhi + off);
                ldsm_x4(al[mi][0], al[mi][1], al[mi][2], al[mi][3], uAlo + off);
            }
            #pragma unroll
            for (int np = 0; np < 2; np++) {
                uint32_t off = ((nw * 32 + np * 16 + bNt * 8 + bLr) * PITCH + ks * 16 + bKof) * 2;
                ldsm_x4(bhr[np][0], bhr[np][1], bhr[np][2], bhr[np][3], uBhi + off);
                ldsm_x4(blr[np][0], blr[np][1], blr[np][2], blr[np][3], uBlo + off);
            }
            #pragma unroll
            for (int mi = 0; mi < 4; mi++)
                #pragma unroll
                for (int ni = 0; ni < 4; ni++) {
                    uint32_t bh0 = bhr[ni >> 1][(ni & 1) * 2];
                    uint32_t bh1 = bhr[ni >> 1][(ni & 1) * 2 + 1];
                    uint32_t bl0 = blr[ni >> 1][(ni & 1) * 2];
                    uint32_t bl1 = blr[ni >> 1][(ni & 1) * 2 + 1];
                    mma_bf16(d[mi][ni], ah[mi], bh0, bh1);
                    mma_bf16(d[mi][ni], ah[mi], bl0, bl1);
                    mma_bf16(d[mi][ni], al[mi], bh0, bh1);
                }
        }
        __syncthreads();
    }

    // epilogue: fragments -> smem C[128][129]
    float* Csh = (float*)sm;
    #pragma unroll
    for (int mi = 0; mi < 4; mi++)
        #pragma unroll
        for (int ni = 0; ni < 4; ni++) {
            int r0 = mw * 64 + mi * 16 + (lane >> 2);
            int c0 = nw * 32 + ni * 8 + (lane & 3) * 2;
            Csh[r0 * 129 + c0]       = d[mi][ni][0];
            Csh[r0 * 129 + c0 + 1]   = d[mi][ni][1];
            Csh[(r0 + 8) * 129 + c0]     = d[mi][ni][2];
            Csh[(r0 + 8) * 129 + c0 + 1] = d[mi][ni][3];
        }
    __syncthreads();

    const float* rn = g_rn + b * Ll;
    float* Cmat = att + (size_t)b * ATT_PER_B;
    int row = tid & 127;
    int half = tid >> 7;            // 0,1 -> columns [half*64, half*64+64)
    {   // forward: att[pBase+row][qBase+c] = Csh[row][c] * rn[qBase+c]
        float4* dst = (float4*)&Cmat[(size_t)(pBase + row) * Ll + qBase + half * 64];
        const float4* rq = (const float4*)(rn + qBase + half * 64);
        const float* src = &Csh[row * 129 + half * 64];
        #pragma unroll
        for (int j = 0; j < 16; j++) {
            float4 rv = rq[j];
            float4 v;
            v.x = src[4*j + 0] * rv.x;
            v.y = src[4*j + 1] * rv.y;
            v.z = src[4*j + 2] * rv.z;
            v.w = src[4*j + 3] * rv.w;
            dst[j] = v;
        }
    }
    if (bi != bj) {  // mirror: att[qBase+row][pBase+c] = Csh[c][row] * rn[pBase+c]
        float4* dst = (float4*)&Cmat[(size_t)(qBase + row) * Ll + pBase + half * 64];
        const float4* rp = (const float4*)(rn + pBase + half * 64);
        #pragma unroll
        for (int j = 0; j < 16; j++) {
            float4 rv = rp[j];
            int c = half * 64 + 4 * j;
            float4 v;
            v.x = Csh[(c + 0) * 129 + row] * rv.x;
            v.y = Csh[(c + 1) * 129 + row] * rv.y;
            v.z = Csh[(c + 2) * 129 + row] * rv.z;
            v.w = Csh[(c + 3) * 129 + row] * rv.w;
            dst[j] = v;
        }
    }
}

// ---------------- stage 6: fuse + softmax over gated columns only ----------------
__global__ __launch_bounds__(256) void k_fuse_softmax(const float* __restrict__ att) {
    int b = blockIdx.y;
    int p = blockIdx.x;
    const float* Sb  = att + (size_t)b * ATT_PER_B;
    int cnt = g_cnt[b];
    const int* idxb = g_idxl + b * Ll;
    float* Arow = g_A + ((size_t)b * Ll + p) * Ll;

    __shared__ float zrow[Ll];
    __shared__ float red[256];

    int i = p >> 6, j = p & 63;
    int t = j * 64 + i;

    int  Pb[3] = {0, 0, 0};
    bool pv[3];
    #pragma unroll
    for (int d = 0; d < 3; d++) {
        int tb = t + d - 1;
        pv[d] = (tb >= 0 && tb < Ll);
        if (pv[d]) Pb[d] = ((tb & 63) << 6) | (tb >> 6);
    }

    float lmax = (cnt < Ll) ? 0.0f : -3.4e38f;
    for (int k = threadIdx.x; k < cnt; k += 256) {
        int q = idxb[k];
        int u = ((q & 63) << 6) | (q >> 6);
        float acc = 0.f;
        #pragma unroll
        for (int d = 0; d < 3; d++) {
            int ub = u + d - 1;
            if (pv[d] && ub >= 0 && ub < Ll) {
                int Q = ((ub & 63) << 6) | (ub >> 6);
                int P = Pb[d];
                #pragma unroll
                for (int a = -1; a <= 1; a++) {
                    int Pa = P + a, Qa = Q + a;
                    if (Pa >= 0 && Pa < Ll && Qa >= 0 && Qa < Ll)
                        acc += Sb[(size_t)Pa * Ll + Qa];
                }
            }
        }
        float val = acc * 10.0f;
        zrow[k] = val;
        lmax = fmaxf(lmax, val);
    }
    red[threadIdx.x] = lmax;
    __syncthreads();
    for (int s = 128; s > 0; s >>= 1) {
        if (threadIdx.x < s) red[threadIdx.x] = fmaxf(red[threadIdx.x], red[threadIdx.x + s]);
        __syncthreads();
    }
    float mx = red[0];
    __syncthreads();

    float lsum = 0.f;
    for (int k = threadIdx.x; k < cnt; k += 256) {
        float e = __expf(zrow[k] - mx);
        zrow[k] = e;
        lsum += e;
    }
    red[threadIdx.x] = lsum;
    __syncthreads();
    for (int s = 128; s > 0; s >>= 1) {
        if (threadIdx.x < s) red[threadIdx.x] += red[threadIdx.x + s];
        __syncthreads();
    }
    float denom = red[0] + (float)(Ll - cnt) * __expf(-mx);
    float inv = 1.0f / denom;
    for (int k = threadIdx.x; k < cnt; k += 256)
        Arow[k] = zrow[k] * inv;
    int kpad = (cnt + 15) & ~15;
    for (int k = cnt + (int)threadIdx.x; k < kpad; k += 256)
        Arow[k] = 0.f;
}

// ---------------- stage 7: GEMM2  M[L,576] = A_compact[L,cnt] * R[idx[cnt],576] ----------------
__global__ __launch_bounds__(256) void k_gemm2() {
    int b  = blockIdx.z;
    int bm = blockIdx.y;
    int bn = blockIdx.x;
    const float* A  = g_A + (size_t)b * Ll * Ll;
    const float* Bm = g_R + (size_t)b * Ll * KK;
    float* Cm = g_M + (size_t)b * Ll * KK;
    int cnt = g_cnt[b];
    int kpad = (cnt + 15) & ~15;
    const int* idxb = g_idxl + b * Ll;

    __shared__ float As[16][128];
    __shared__ float Bs[16][64];

    int tid = threadIdx.x;
    int tx = tid & 15, ty = tid >> 4;
    int mBase = bm * 128, nBase = bn * 64;

    float acc[8][4];
    #pragma unroll
    for (int u = 0; u < 8; u++)
        #pragma unroll
        for (int v = 0; v < 4; v++) acc[u][v] = 0.f;

    int r  = tid >> 2;
    int kc = (tid & 3) * 4;
    int br = tid >> 4;
    int bc = (tid & 15) * 4;

    for (int k0 = 0; k0 < kpad; k0 += 16) {
        float4 a0 = *(const float4*)&A[(size_t)(mBase + r)      * Ll + k0 + kc];
        float4 a1 = *(const float4*)&A[(size_t)(mBase + r + 64) * Ll + k0 + kc];
        As[kc+0][r]    = a0.x; As[kc+1][r]    = a0.y; As[kc+2][r]    = a0.z; As[kc+3][r]    = a0.w;
        As[kc+0][r+64] = a1.x; As[kc+1][r+64] = a1.y; As[kc+2][r+64] = a1.z; As[kc+3][r+64] = a1.w;
        int kg = k0 + br;
        float4 bv = make_float4(0.f, 0.f, 0.f, 0.f);
        if (kg < cnt)
            bv = *(const float4*)&Bm[(size_t)idxb[kg] * KK + nBase + bc];
        *(float4*)&Bs[br][bc] = bv;
        __syncthreads();
        #pragma unroll
        for (int k = 0; k < 16; k++) {
            float4 ar0 = *(const float4*)&As[k][ty*8];
            float4 ar1 = *(const float4*)&As[k][ty*8 + 4];
            float4 brv = *(const float4*)&Bs[k][tx*4];
            float ar[8] = {ar0.x, ar0.y, ar0.z, ar0.w, ar1.x, ar1.y, ar1.z, ar1.w};
            float brg[4] = {brv.x, brv.y, brv.z, brv.w};
            #pragma unroll
            for (int u = 0; u < 8; u++)
                #pragma unroll
                for (int v = 0; v < 4; v++) acc[u][v] += ar[u] * brg[v];
        }
        __syncthreads();
    }
    #pragma unroll
    for (int u = 0; u < 8; u++) {
        float4 w = make_float4(acc[u][0], acc[u][1], acc[u][2], acc[u][3]);
        *(float4*)&Cm[(size_t)(mBase + ty*8 + u) * KK + nBase + tx*4] = w;
    }
}

// ---------------- stage 8: scatter (adjoint of stride-2 SAME conv), /4 ----------------
__global__ void k_scatter(float* __restrict__ y) {
    int idx = blockIdx.x * blockDim.x + threadIdx.x;
    const int total = Bsz * Hf * Wf * (Cc / 4);
    if (idx >= total) return;
    int c4 = idx & 15;
    int qq = (idx >> 4) & 127;
    int pp = (idx >> 11) & 127;
    int b  = idx >> 18;

    const float* Mb = g_M + (size_t)b * Ll * KK;

    int icand[2], khc[2], nci = 0;
    if ((pp & 1) == 0) {
        icand[nci] = pp >> 1; khc[nci] = 0; nci++;
        if (pp >= 2) { icand[nci] = (pp >> 1) - 1; khc[nci] = 2; nci++; }
    } else { icand[0] = pp >> 1; khc[0] = 1; nci = 1; }

    int jcand[2], kwc[2], ncj = 0;
    if ((qq & 1) == 0) {
        jcand[ncj] = qq >> 1; kwc[ncj] = 0; ncj++;
        if (qq >= 2) { jcand[ncj] = (qq >> 1) - 1; kwc[ncj] = 2; ncj++; }
    } else { jcand[0] = qq >> 1; kwc[0] = 1; ncj = 1; }

    float4 s = make_float4(0.f, 0.f, 0.f, 0.f);
    for (int a = 0; a < nci; a++)
        for (int c = 0; c < ncj; c++) {
            const float4 v = *(const float4*)&Mb[(size_t)(icand[a] * 64 + jcand[c]) * KK
                                                 + (khc[a] * 3 + kwc[c]) * 64 + c4 * 4];
            s.x += v.x; s.y += v.y; s.z += v.z; s.w += v.w;
        }
    s.x *= 0.25f; s.y *= 0.25f; s.z *= 0.25f; s.w *= 0.25f;
    ((float4*)y)[idx] = s;
}

// ---------------- launch ----------------
extern "C" void kernel_launch(void* const* d_in, const int* in_sizes, int n_in,
                              void* d_out, int out_size) {
    const float* x    = (const float*)d_in[0];
    const float* mask = (const float*)d_in[1];
    float* out = (float*)d_out;
    float* y   = out;
    float* att = out + Y_ELEMS;

    cudaFuncSetAttribute(k_gemm1_mma, cudaFuncAttributeMaxDynamicSharedMemorySize, G1_SMEM);

    k_avgpool   <<<(Bsz*hh*ww*Cc + 255) / 256, 256>>>(x, mask);
    k_im2col_f  <<<(Bsz*Ll*KK + 255) / 256, 256>>>();
    k_im2col_raw<<<(Bsz*Ll*KK + 255) / 256, 256>>>(x);
    k_norm      <<<(Bsz*Ll*32 + 255) / 256, 256>>>();
    k_mmgate    <<<(Bsz*Ll + 255) / 256, 256>>>();
    k_compact   <<<Bsz, 256>>>();
    k_gemm1_mma <<<dim3(32, 32, Bsz), 256, G1_SMEM>>>(att);
    k_fuse_softmax<<<dim3(Ll, Bsz), 256>>>(att);
    k_gemm2     <<<dim3(9, 32, Bsz), 256>>>();
    k_scatter   <<<(Bsz*Hf*Wf*16 + 255) / 256, 256>>>(y);
}

// round 5
// speedup vs baseline: 3.8031x; 1.2174x over previous
#include <cuda_runtime.h>
#include <cuda_bf16.h>
#include <cstdint>

// ---------------- problem constants ----------------
#define Bsz 2
#define Hf 128
#define Wf 128
#define Cc 64
#define hh 64
#define ww 64
#define Ll 4096          // hh*ww
#define KK 576           // 3*3*64
#define Y_ELEMS (Bsz*Hf*Wf*Cc)        // 2097152
#define ATT_PER_B ((size_t)Ll*Ll)     // 16777216

// ---------------- scratch (static device globals; no allocation) ----------------
__device__ float g_f[Bsz*hh*ww*Cc];        // low-res image
__device__ float g_m[Bsz*hh*ww];           // low-res mask
__device__ float g_rn[Bsz*Ll];             // 1/max(norm,1e-4)
__device__ float g_mm[Bsz*Ll];             // gate
__device__ int   g_cnt[Bsz];               // # gated columns
__device__ int   g_idxl[Bsz*Ll];           // compacted gated column indices
__device__ __align__(256) __nv_bfloat16 g_Phi[Bsz*Ll*KK]; // patches, bf16 hi
__device__ __align__(256) __nv_bfloat16 g_Plo[Bsz*Ll*KK]; // patches, bf16 lo
__device__ __align__(256) __nv_bfloat16 g_Rhi[Bsz*Ll*KK]; // raw patches, bf16 hi
__device__ __align__(256) __nv_bfloat16 g_Rlo[Bsz*Ll*KK]; // raw patches, bf16 lo
__device__ __align__(256) __nv_bfloat16 g_Ahi[(size_t)Bsz*Ll*Ll]; // attn probs hi (compacted)
__device__ __align__(256) __nv_bfloat16 g_Alo[(size_t)Bsz*Ll*Ll]; // attn probs lo
__device__ float g_M[Bsz*Ll*KK];           // GEMM2 result

// ---------------- warp-mma helpers (baseline PTX, no 'a' features) ----------------
__device__ __forceinline__ uint32_t smem_u32(const void* p) {
    uint32_t a;
    asm("{ .reg .u64 t; cvta.to.shared.u64 t, %1; cvt.u32.u64 %0, t; }" : "=r"(a) : "l"(p));
    return a;
}
__device__ __forceinline__ void ldsm_x4(uint32_t& r0, uint32_t& r1, uint32_t& r2, uint32_t& r3,
                                        uint32_t addr) {
    asm volatile("ldmatrix.sync.aligned.m8n8.x4.shared.b16 {%0,%1,%2,%3}, [%4];"
                 : "=r"(r0), "=r"(r1), "=r"(r2), "=r"(r3) : "r"(addr));
}
__device__ __forceinline__ void mma_bf16(float* d, const uint32_t* a, uint32_t b0, uint32_t b1) {
    asm volatile(
        "mma.sync.aligned.m16n8k16.row.col.f32.bf16.bf16.f32 "
        "{%0,%1,%2,%3}, {%4,%5,%6,%7}, {%8,%9}, {%0,%1,%2,%3};"
        : "+f"(d[0]), "+f"(d[1]), "+f"(d[2]), "+f"(d[3])
        : "r"(a[0]), "r"(a[1]), "r"(a[2]), "r"(a[3]), "r"(b0), "r"(b1));
}

// ---------------- stage 0: avgpool x->f, mask->m ----------------
__global__ void k_avgpool(const float* __restrict__ x, const float* __restrict__ mask) {
    int idx = blockIdx.x * blockDim.x + threadIdx.x;
    const int total = Bsz * hh * ww * Cc;
    if (idx < total) {
        int c = idx % Cc;
        int j = (idx / Cc) % ww;
        int i = (idx / (Cc * ww)) % hh;
        int b = idx / (Cc * ww * hh);
        const float* xb = x + (size_t)b * Hf * Wf * Cc;
        float s = xb[((2*i)   * Wf + 2*j  ) * Cc + c]
                + xb[((2*i)   * Wf + 2*j+1) * Cc + c]
                + xb[((2*i+1) * Wf + 2*j  ) * Cc + c]
                + xb[((2*i+1) * Wf + 2*j+1) * Cc + c];
        g_f[idx] = 0.25f * s;
    }
    if (idx < Bsz * hh * ww) {
        int j = idx % ww;
        int i = (idx / ww) % hh;
        int b = idx / (ww * hh);
        const float* mb = mask + (size_t)b * Hf * Wf;
        float s = mb[(2*i)*Wf + 2*j] + mb[(2*i)*Wf + 2*j+1]
                + mb[(2*i+1)*Wf + 2*j] + mb[(2*i+1)*Wf + 2*j+1];
        g_m[idx] = 0.25f * s;
    }
}

// ---------------- stage 1: im2col of f -> bf16 hi/lo split ----------------
__global__ void k_im2col_f() {
    int idx = blockIdx.x * blockDim.x + threadIdx.x;
    const int total = Bsz * Ll * KK;
    if (idx >= total) return;
    int kk = idx % KK;
    int p  = (idx / KK) % Ll;
    int b  = idx / (KK * Ll);
    int c  = kk % 64;
    int dw = (kk / 64) % 3;
    int dh = kk / 192;
    int i = p >> 6, j = p & 63;
    int ri = i - 1 + dh, rj = j - 1 + dw;
    float v = 0.f;
    if (ri >= 0 && ri < hh && rj >= 0 && rj < ww)
        v = g_f[(((size_t)b * hh + ri) * ww + rj) * Cc + c];
    __nv_bfloat16 hv = __float2bfloat16(v);
    g_Phi[idx] = hv;
    g_Plo[idx] = __float2bfloat16(v - __bfloat162float(hv));
}

// ---------------- stage 2: im2col of raw x -> bf16 hi/lo ----------------
__global__ void k_im2col_raw(const float* __restrict__ x) {
    int idx = blockIdx.x * blockDim.x + threadIdx.x;
    const int total = Bsz * Ll * KK;
    if (idx >= total) return;
    int kk = idx % KK;
    int p  = (idx / KK) % Ll;
    int b  = idx / (KK * Ll);
    int c  = kk % 64;
    int dw = (kk / 64) % 3;
    int dh = kk / 192;
    int i = p >> 6, j = p & 63;
    int ri = 2*i + dh, rj = 2*j + dw;   // pad only on bottom/right
    float v = 0.f;
    if (ri < Hf && rj < Wf)
        v = x[(((size_t)b * Hf + ri) * Wf + rj) * Cc + c];
    __nv_bfloat16 hv = __float2bfloat16(v);
    g_Rhi[idx] = hv;
    g_Rlo[idx] = __float2bfloat16(v - __bfloat162float(hv));
}

// ---------------- stage 3: patch norms (from hi+lo) ----------------
__global__ void k_norm() {
    int gt = blockIdx.x * blockDim.x + threadIdx.x;
    int warp = gt >> 5;
    int lane = gt & 31;
    if (warp >= Bsz * Ll) return;
    const __nv_bfloat16* rh = g_Phi + (size_t)warp * KK;
    const __nv_bfloat16* rl = g_Plo + (size_t)warp * KK;
    float s = 0.f;
    for (int k = lane; k < KK; k += 32) {
        float v = __bfloat162float(rh[k]) + __bfloat162float(rl[k]);
        s += v * v;
    }
    #pragma unroll
    for (int o = 16; o > 0; o >>= 1) s += __shfl_xor_sync(0xffffffff, s, o);
    if (lane == 0) g_rn[warp] = 1.0f / fmaxf(sqrtf(s), 1e-4f);
}

// ---------------- stage 4: mask gate ----------------
__global__ void k_mmgate() {
    int idx = blockIdx.x * blockDim.x + threadIdx.x;
    if (idx >= Bsz * Ll) return;
    int q = idx % Ll;
    int b = idx / Ll;
    int i = q >> 6, j = q & 63;
    float s = 0.f;
    for (int dh = 0; dh < 3; dh++)
        for (int dw = 0; dw < 3; dw++) {
            int ri = i - 1 + dh, rj = j - 1 + dw;
            if (ri >= 0 && ri < hh && rj >= 0 && rj < ww)
                s += g_m[((size_t)b * hh + ri) * ww + rj];
        }
    g_mm[idx] = ((s / 9.0f) == 1.0f) ? 1.0f : 0.0f;
}

// ---------------- stage 4b: compact gated columns ----------------
__global__ __launch_bounds__(256) void k_compact() {
    int b = blockIdx.x;
    __shared__ int cnts[256];
    __shared__ int offs[257];
    int t = threadIdx.x;
    const float* mmb = g_mm + b * Ll;
    int base = t * 16;
    int local = 0;
    #pragma unroll
    for (int e = 0; e < 16; e++) local += (mmb[base + e] != 0.f) ? 1 : 0;
    cnts[t] = local;
    __syncthreads();
    if (t == 0) {
        int run = 0;
        for (int s = 0; s < 256; s++) { offs[s] = run; run += cnts[s]; }
        offs[256] = run;
        g_cnt[b] = run;
    }
    __syncthreads();
    int o = offs[t];
    int* idxb = g_idxl + b * Ll;
    #pragma unroll
    for (int e = 0; e < 16; e++)
        if (mmb[base + e] != 0.f) idxb[o++] = base + e;
}

// ---------------- stage 5: GEMM1 via mma.sync bf16 hi/lo (symmetric syrk) ----------------
#define PITCH 72
#define ARR_B (128 * PITCH * 2)       // 18432 bytes
#define G1_SMEM (4 * ARR_B)           // 73728 bytes
__global__ __launch_bounds__(256, 1) void k_gemm1_mma(float* __restrict__ att) {
    int b  = blockIdx.z;
    int bi = blockIdx.y;
    int bj = blockIdx.x;
    if (bj < bi) return;

    extern __shared__ char sm[];
    __nv_bfloat16* sAhi = (__nv_bfloat16*)(sm);
    __nv_bfloat16* sAlo = (__nv_bfloat16*)(sm + ARR_B);
    __nv_bfloat16* sBhi = (__nv_bfloat16*)(sm + 2 * ARR_B);
    __nv_bfloat16* sBlo = (__nv_bfloat16*)(sm + 3 * ARR_B);
    uint32_t uAhi = smem_u32(sAhi), uAlo = smem_u32(sAlo);
    uint32_t uBhi = smem_u32(sBhi), uBlo = smem_u32(sBlo);

    int tid = threadIdx.x;
    int wid = tid >> 5;
    int lane = tid & 31;
    int mw = wid >> 2;       // 0..1
    int nw = wid & 3;        // 0..3

    const __nv_bfloat16* Phi = g_Phi + (size_t)b * Ll * KK;
    const __nv_bfloat16* Plo = g_Plo + (size_t)b * Ll * KK;
    int pBase = bi * 128, qBase = bj * 128;

    float d[4][4][4];
    #pragma unroll
    for (int mi = 0; mi < 4; mi++)
        #pragma unroll
        for (int ni = 0; ni < 4; ni++)
            #pragma unroll
            for (int e = 0; e < 4; e++) d[mi][ni][e] = 0.f;

    int aRow = lane & 15;
    int aKof = ((lane >> 4) & 1) * 8;
    int bGrp = lane >> 3;
    int bLr  = lane & 7;
    int bNt  = bGrp >> 1;
    int bKof = (bGrp & 1) * 8;

    #pragma unroll 1
    for (int ch = 0; ch < 9; ch++) {
        int k0 = ch * 64;
        #pragma unroll
        for (int it = 0; it < 4; it++) {
            int idx = it * 256 + tid;
            int row = idx >> 3;
            int c4  = idx & 7;
            size_t goffA = (size_t)(pBase + row) * KK + k0 + c4 * 8;
            size_t goffB = (size_t)(qBase + row) * KK + k0 + c4 * 8;
            int soff = row * PITCH + c4 * 8;
            *(uint4*)&sAhi[soff] = *(const uint4*)&Phi[goffA];
            *(uint4*)&sAlo[soff] = *(const uint4*)&Plo[goffA];
            *(uint4*)&sBhi[soff] = *(const uint4*)&Phi[goffB];
            *(uint4*)&sBlo[soff] = *(const uint4*)&Plo[goffB];
        }
        __syncthreads();

        #pragma unroll
        for (int ks = 0; ks < 4; ks++) {
            uint32_t ah[4][4], al[4][4], bhr[2][4], blr[2][4];
            #pragma unroll
            for (int mi = 0; mi < 4; mi++) {
                uint32_t off = ((mw * 64 + mi * 16 + aRow) * PITCH + ks * 16 + aKof) * 2;
                ldsm_x4(ah[mi][0], ah[mi][1], ah[mi][2], ah[mi][3], uAhi + off);
                ldsm_x4(al[mi][0], al[mi][1], al[mi][2], al[mi][3], uAlo + off);
            }
            #pragma unroll
            for (int np = 0; np < 2; np++) {
                uint32_t off = ((nw * 32 + np * 16 + bNt * 8 + bLr) * PITCH + ks * 16 + bKof) * 2;
                ldsm_x4(bhr[np][0], bhr[np][1], bhr[np][2], bhr[np][3], uBhi + off);
                ldsm_x4(blr[np][0], blr[np][1], blr[np][2], blr[np][3], uBlo + off);
            }
            #pragma unroll
            for (int mi = 0; mi < 4; mi++)
                #pragma unroll
                for (int ni = 0; ni < 4; ni++) {
                    uint32_t bh0 = bhr[ni >> 1][(ni & 1) * 2];
                    uint32_t bh1 = bhr[ni >> 1][(ni & 1) * 2 + 1];
                    uint32_t bl0 = blr[ni >> 1][(ni & 1) * 2];
                    uint32_t bl1 = blr[ni >> 1][(ni & 1) * 2 + 1];
                    mma_bf16(d[mi][ni], ah[mi], bh0, bh1);
                    mma_bf16(d[mi][ni], ah[mi], bl0, bl1);
                    mma_bf16(d[mi][ni], al[mi], bh0, bh1);
                }
        }
        __syncthreads();
    }

    // epilogue: fragments -> smem C[128][129]
    float* Csh = (float*)sm;
    #pragma unroll
    for (int mi = 0; mi < 4; mi++)
        #pragma unroll
        for (int ni = 0; ni < 4; ni++) {
            int r0 = mw * 64 + mi * 16 + (lane >> 2);
            int c0 = nw * 32 + ni * 8 + (lane & 3) * 2;
            Csh[r0 * 129 + c0]       = d[mi][ni][0];
            Csh[r0 * 129 + c0 + 1]   = d[mi][ni][1];
            Csh[(r0 + 8) * 129 + c0]     = d[mi][ni][2];
            Csh[(r0 + 8) * 129 + c0 + 1] = d[mi][ni][3];
        }
    __syncthreads();

    const float* rn = g_rn + b * Ll;
    float* Cmat = att + (size_t)b * ATT_PER_B;
    int row = tid & 127;
    int half = tid >> 7;
    {
        float4* dst = (float4*)&Cmat[(size_t)(pBase + row) * Ll + qBase + half * 64];
        const float4* rq = (const float4*)(rn + qBase + half * 64);
        const float* src = &Csh[row * 129 + half * 64];
        #pragma unroll
        for (int j = 0; j < 16; j++) {
            float4 rv = rq[j];
            float4 v;
            v.x = src[4*j + 0] * rv.x;
            v.y = src[4*j + 1] * rv.y;
            v.z = src[4*j + 2] * rv.z;
            v.w = src[4*j + 3] * rv.w;
            dst[j] = v;
        }
    }
    if (bi != bj) {
        float4* dst = (float4*)&Cmat[(size_t)(qBase + row) * Ll + pBase + half * 64];
        const float4* rp = (const float4*)(rn + pBase + half * 64);
        #pragma unroll
        for (int j = 0; j < 16; j++) {
            float4 rv = rp[j];
            int c = half * 64 + 4 * j;
            float4 v;
            v.x = Csh[(c + 0) * 129 + row] * rv.x;
            v.y = Csh[(c + 1) * 129 + row] * rv.y;
            v.z = Csh[(c + 2) * 129 + row] * rv.z;
            v.w = Csh[(c + 3) * 129 + row] * rv.w;
            dst[j] = v;
        }
    }
}

// ---------------- stage 6: fuse + softmax over gated columns -> bf16 hi/lo compacted ----------------
__global__ __launch_bounds__(256) void k_fuse_softmax(const float* __restrict__ att) {
    int b = blockIdx.y;
    int p = blockIdx.x;
    const float* Sb  = att + (size_t)b * ATT_PER_B;
    int cnt = g_cnt[b];
    const int* idxb = g_idxl + b * Ll;
    __nv_bfloat16* Ahi = g_Ahi + ((size_t)b * Ll + p) * Ll;
    __nv_bfloat16* Alo = g_Alo + ((size_t)b * Ll + p) * Ll;

    __shared__ float zrow[Ll];
    __shared__ float red[256];

    int i = p >> 6, j = p & 63;
    int t = j * 64 + i;

    int  Pb[3] = {0, 0, 0};
    bool pv[3];
    #pragma unroll
    for (int d = 0; d < 3; d++) {
        int tb = t + d - 1;
        pv[d] = (tb >= 0 && tb < Ll);
        if (pv[d]) Pb[d] = ((tb & 63) << 6) | (tb >> 6);
    }

    float lmax = (cnt < Ll) ? 0.0f : -3.4e38f;
    for (int k = threadIdx.x; k < cnt; k += 256) {
        int q = idxb[k];
        int u = ((q & 63) << 6) | (q >> 6);
        float acc = 0.f;
        #pragma unroll
        for (int d = 0; d < 3; d++) {
            int ub = u + d - 1;
            if (pv[d] && ub >= 0 && ub < Ll) {
                int Q = ((ub & 63) << 6) | (ub >> 6);
                int P = Pb[d];
                #pragma unroll
                for (int a = -1; a <= 1; a++) {
                    int Pa = P + a, Qa = Q + a;
                    if (Pa >= 0 && Pa < Ll && Qa >= 0 && Qa < Ll)
                        acc += Sb[(size_t)Pa * Ll + Qa];
                }
            }
        }
        float val = acc * 10.0f;
        zrow[k] = val;
        lmax = fmaxf(lmax, val);
    }
    red[threadIdx.x] = lmax;
    __syncthreads();
    for (int s = 128; s > 0; s >>= 1) {
        if (threadIdx.x < s) red[threadIdx.x] = fmaxf(red[threadIdx.x], red[threadIdx.x + s]);
        __syncthreads();
    }
    float mx = red[0];
    __syncthreads();

    float lsum = 0.f;
    for (int k = threadIdx.x; k < cnt; k += 256) {
        float e = __expf(zrow[k] - mx);
        zrow[k] = e;
        lsum += e;
    }
    red[threadIdx.x] = lsum;
    __syncthreads();
    for (int s = 128; s > 0; s >>= 1) {
        if (threadIdx.x < s) red[threadIdx.x] += red[threadIdx.x + s];
        __syncthreads();
    }
    float denom = red[0] + (float)(Ll - cnt) * __expf(-mx);
    float inv = 1.0f / denom;
    for (int k = threadIdx.x; k < cnt; k += 256) {
        float v = zrow[k] * inv;
        __nv_bfloat16 hv = __float2bfloat16(v);
        Ahi[k] = hv;
        Alo[k] = __float2bfloat16(v - __bfloat162float(hv));
    }
    int kp64 = (cnt + 63) & ~63;
    for (int k = cnt + (int)threadIdx.x; k < kp64; k += 256) {
        Ahi[k] = __float2bfloat16(0.f);
        Alo[k] = __float2bfloat16(0.f);
    }
}

// ---------------- stage 7: GEMM2 via mma.sync bf16 hi/lo ----------------
// M[L,576] = A_compact[L,kp] * R[idx[k],576]
// smem: sA2hi/sA2lo 128x72, sB2hi/sB2lo 64x72 (B stored [n][k])
#define A2_B (128 * PITCH * 2)   // 18432
#define B2_B (64 * PITCH * 2)    // 9216
#define G2_SMEM (2 * A2_B + 2 * B2_B)  // 55296
__global__ __launch_bounds__(256, 2) void k_gemm2_mma() {
    int b  = blockIdx.z;
    int bm = blockIdx.y;   // 0..31
    int bn = blockIdx.x;   // 0..8
    int cnt = g_cnt[b];
    int kp = (cnt + 63) & ~63;
    const int* idxb = g_idxl + b * Ll;
    const __nv_bfloat16* Ahi = g_Ahi + (size_t)b * Ll * Ll;
    const __nv_bfloat16* Alo = g_Alo + (size_t)b * Ll * Ll;
    const __nv_bfloat16* Rhi = g_Rhi + (size_t)b * Ll * KK;
    const __nv_bfloat16* Rlo = g_Rlo + (size_t)b * Ll * KK;
    float* Cm = g_M + (size_t)b * Ll * KK;

    extern __shared__ char sm2[];
    __nv_bfloat16* sAh = (__nv_bfloat16*)(sm2);
    __nv_bfloat16* sAl = (__nv_bfloat16*)(sm2 + A2_B);
    __nv_bfloat16* sBh = (__nv_bfloat16*)(sm2 + 2 * A2_B);
    __nv_bfloat16* sBl = (__nv_bfloat16*)(sm2 + 2 * A2_B + B2_B);
    uint32_t uAh = smem_u32(sAh), uAl = smem_u32(sAl);
    uint32_t uBh = smem_u32(sBh), uBl = smem_u32(sBl);

    int tid = threadIdx.x;
    int wid = tid >> 5;
    int lane = tid & 31;
    int mw = wid >> 1;   // 0..3 (32 rows each)
    int nw = wid & 1;    // 0..1 (32 cols each)
    int mBase = bm * 128, nBase = bn * 64;

    float d[2][4][4];
    #pragma unroll
    for (int mi = 0; mi < 2; mi++)
        #pragma unroll
        for (int ni = 0; ni < 4; ni++)
            #pragma unroll
            for (int e = 0; e < 4; e++) d[mi][ni][e] = 0.f;

    int aRow = lane & 15;
    int aKof = ((lane >> 4) & 1) * 8;
    int bGrp = lane >> 3;
    int bLr  = lane & 7;
    int bNt  = bGrp >> 1;
    int bKof = (bGrp & 1) * 8;

    // loader indices
    int arow = tid >> 1, ahalf = tid & 1;       // A: 128 rows x 2 halves of 32 bf16
    int kg = tid & 63, seg = tid >> 6;          // B: 64 k-rows x 4 segs of 16 n

    #pragma unroll 1
    for (int k0 = 0; k0 < kp; k0 += 64) {
        {   // A tile: [row][k] contiguous
            const uint4* pH = (const uint4*)&Ahi[(size_t)(mBase + arow) * Ll + k0 + ahalf * 32];
            const uint4* pL = (const uint4*)&Alo[(size_t)(mBase + arow) * Ll + k0 + ahalf * 32];
            int soff = arow * PITCH + ahalf * 32;
            #pragma unroll
            for (int jj = 0; jj < 4; jj++) {
                *(uint4*)&sAh[soff + jj * 8] = pH[jj];
                *(uint4*)&sAl[soff + jj * 8] = pL[jj];
            }
        }
        {   // B tile: gather row idx[k0+kg], transpose-store Bs[n][kg]
            int krow = (k0 + kg < cnt) ? idxb[k0 + kg] : 0;
            const uint4* pH = (const uint4*)&Rhi[(size_t)krow * KK + nBase + seg * 16];
            const uint4* pL = (const uint4*)&Rlo[(size_t)krow * KK + nBase + seg * 16];
            __nv_bfloat16 th[16], tl[16];
            *(uint4*)&th[0] = pH[0]; *(uint4*)&th[8] = pH[1];
            *(uint4*)&tl[0] = pL[0]; *(uint4*)&tl[8] = pL[1];
            #pragma unroll
            for (int n = 0; n < 16; n++) {
                sBh[(seg * 16 + n) * PITCH + kg] = th[n];
                sBl[(seg * 16 + n) * PITCH + kg] = tl[n];
            }
        }
        __syncthreads();

        #pragma unroll
        for (int ks = 0; ks < 4; ks++) {
            uint32_t ah[2][4], al[2][4], bhr[2][4], blr[2][4];
            #pragma unroll
            for (int mi = 0; mi < 2; mi++) {
                uint32_t off = ((mw * 32 + mi * 16 + aRow) * PITCH + ks * 16 + aKof) * 2;
                ldsm_x4(ah[mi][0], ah[mi][1], ah[mi][2], ah[mi][3], uAh + off);
                ldsm_x4(al[mi][0], al[mi][1], al[mi][2], al[mi][3], uAl + off);
            }
            #pragma unroll
            for (int np = 0; np < 2; np++) {
                uint32_t off = ((nw * 32 + np * 16 + bNt * 8 + bLr) * PITCH + ks * 16 + bKof) * 2;
                ldsm_x4(bhr[np][0], bhr[np][1], bhr[np][2], bhr[np][3], uBh + off);
                ldsm_x4(blr[np][0], blr[np][1], blr[np][2], blr[np][3], uBl + off);
            }
            #pragma unroll
            for (int mi = 0; mi < 2; mi++)
                #pragma unroll
                for (int ni = 0; ni < 4; ni++) {
                    uint32_t bh0 = bhr[ni >> 1][(ni & 1) * 2];
                    uint32_t bh1 = bhr[ni >> 1][(ni & 1) * 2 + 1];
                    uint32_t bl0 = blr[ni >> 1][(ni & 1) * 2];
                    uint32_t bl1 = blr[ni >> 1][(ni & 1) * 2 + 1];
                    mma_bf16(d[mi][ni], ah[mi], bh0, bh1);
                    mma_bf16(d[mi][ni], ah[mi], bl0, bl1);
                    mma_bf16(d[mi][ni], al[mi], bh0, bh1);
                }
        }
        __syncthreads();
    }

    // epilogue: write fragments directly
    #pragma unroll
    for (int mi = 0; mi < 2; mi++)
        #pragma unroll
        for (int ni = 0; ni < 4; ni++) {
            int r0 = mBase + mw * 32 + mi * 16 + (lane >> 2);
            int c0 = nBase + nw * 32 + ni * 8 + (lane & 3) * 2;
            *(float2*)&Cm[(size_t)r0 * KK + c0]       = make_float2(d[mi][ni][0], d[mi][ni][1]);
            *(float2*)&Cm[(size_t)(r0 + 8) * KK + c0] = make_float2(d[mi][ni][2], d[mi][ni][3]);
        }
}

// ---------------- stage 8: scatter (adjoint of stride-2 SAME conv), /4 ----------------
__global__ void k_scatter(float* __restrict__ y) {
    int idx = blockIdx.x * blockDim.x + threadIdx.x;
    const int total = Bsz * Hf * Wf * (Cc / 4);
    if (idx >= total) return;
    int c4 = idx & 15;
    int qq = (idx >> 4) & 127;
    int pp = (idx >> 11) & 127;
    int b  = idx >> 18;

    const float* Mb = g_M + (size_t)b * Ll * KK;

    int icand[2], khc[2], nci = 0;
    if ((pp & 1) == 0) {
        icand[nci] = pp >> 1; khc[nci] = 0; nci++;
        if (pp >= 2) { icand[nci] = (pp >> 1) - 1; khc[nci] = 2; nci++; }
    } else { icand[0] = pp >> 1; khc[0] = 1; nci = 1; }

    int jcand[2], kwc[2], ncj = 0;
    if ((qq & 1) == 0) {
        jcand[ncj] = qq >> 1; kwc[ncj] = 0; ncj++;
        if (qq >= 2) { jcand[ncj] = (qq >> 1) - 1; kwc[ncj] = 2; ncj++; }
    } else { jcand[0] = qq >> 1; kwc[0] = 1; ncj = 1; }

    float4 s = make_float4(0.f, 0.f, 0.f, 0.f);
    for (int a = 0; a < nci; a++)
        for (int c = 0; c < ncj; c++) {
            const float4 v = *(const float4*)&Mb[(size_t)(icand[a] * 64 + jcand[c]) * KK
                                                 + (khc[a] * 3 + kwc[c]) * 64 + c4 * 4];
            s.x += v.x; s.y += v.y; s.z += v.z; s.w += v.w;
        }
    s.x *= 0.25f; s.y *= 0.25f; s.z *= 0.25f; s.w *= 0.25f;
    ((float4*)y)[idx] = s;
}

// ---------------- launch ----------------
extern "C" void kernel_launch(void* const* d_in, const int* in_sizes, int n_in,
                              void* d_out, int out_size) {
    const float* x    = (const float*)d_in[0];
    const float* mask = (const float*)d_in[1];
    float* out = (float*)d_out;
    float* y   = out;
    float* att = out + Y_ELEMS;

    cudaFuncSetAttribute(k_gemm1_mma, cudaFuncAttributeMaxDynamicSharedMemorySize, G1_SMEM);
    cudaFuncSetAttribute(k_gemm2_mma, cudaFuncAttributeMaxDynamicSharedMemorySize, G2_SMEM);

    k_avgpool   <<<(Bsz*hh*ww*Cc + 255) / 256, 256>>>(x, mask);
    k_im2col_f  <<<(Bsz*Ll*KK + 255) / 256, 256>>>();
    k_im2col_raw<<<(Bsz*Ll*KK + 255) / 256, 256>>>(x);
    k_norm      <<<(Bsz*Ll*32 + 255) / 256, 256>>>();
    k_mmgate    <<<(Bsz*Ll + 255) / 256, 256>>>();
    k_compact   <<<Bsz, 256>>>();
    k_gemm1_mma <<<dim3(32, 32, Bsz), 256, G1_SMEM>>>(att);
    k_fuse_softmax<<<dim3(Ll, Bsz), 256>>>(att);
    k_gemm2_mma <<<dim3(9, 32, Bsz), 256, G2_SMEM>>>();
    k_scatter   <<<(Bsz*Hf*Wf*16 + 255) / 256, 256>>>(y);
}

// round 7
// speedup vs baseline: 4.0371x; 1.0615x over previous
#include <cuda_runtime.h>
#include <cuda_bf16.h>
#include <cstdint>

// ---------------- problem constants ----------------
#define Bsz 2
#define Hf 128
#define Wf 128
#define Cc 64
#define hh 64
#define ww 64
#define Ll 4096          // hh*ww
#define KK 576           // 3*3*64
#define Y_ELEMS (Bsz*Hf*Wf*Cc)        // 2097152
#define ATT_PER_B ((size_t)Ll*Ll)     // 16777216

// ---------------- scratch (static device globals; no allocation) ----------------
__device__ float g_f[Bsz*hh*ww*Cc];        // low-res image
__device__ float g_m[Bsz*hh*ww];           // low-res mask
__device__ float g_ssq[Bsz*Ll];            // per-pixel sum of squares
__device__ float g_rn[Bsz*Ll];             // 1/max(norm,1e-4)
__device__ float g_mm[Bsz*Ll];             // gate
__device__ int   g_cnt[Bsz];               // # gated columns
__device__ int   g_idxl[Bsz*Ll];           // compacted gated column indices
__device__ __align__(256) __nv_bfloat16 g_Phi[Bsz*Ll*KK]; // patches, bf16 hi
__device__ __align__(256) __nv_bfloat16 g_Plo[Bsz*Ll*KK]; // patches, bf16 lo
__device__ __align__(256) __nv_bfloat16 g_Rhi[Bsz*Ll*KK]; // raw patches, bf16 hi
__device__ __align__(256) __nv_bfloat16 g_Rlo[Bsz*Ll*KK]; // raw patches, bf16 lo
__device__ __align__(256) __nv_bfloat16 g_Ahi[(size_t)Bsz*Ll*Ll]; // attn probs hi (compacted)
__device__ __align__(256) __nv_bfloat16 g_Alo[(size_t)Bsz*Ll*Ll]; // attn probs lo
__device__ float g_M[Bsz*Ll*KK];           // GEMM2 result

// ---------------- helpers ----------------
__device__ __forceinline__ uint32_t smem_u32(const void* p) {
    uint32_t a;
    asm("{ .reg .u64 t; cvta.to.shared.u64 t, %1; cvt.u32.u64 %0, t; }" : "=r"(a) : "l"(p));
    return a;
}
__device__ __forceinline__ void ldsm_x4(uint32_t& r0, uint32_t& r1, uint32_t& r2, uint32_t& r3,
                                        uint32_t addr) {
    asm volatile("ldmatrix.sync.aligned.m8n8.x4.shared.b16 {%0,%1,%2,%3}, [%4];"
                 : "=r"(r0), "=r"(r1), "=r"(r2), "=r"(r3) : "r"(addr));
}
__device__ __forceinline__ void mma_bf16(float* d, const uint32_t* a, uint32_t b0, uint32_t b1) {
    asm volatile(
        "mma.sync.aligned.m16n8k16.row.col.f32.bf16.bf16.f32 "
        "{%0,%1,%2,%3}, {%4,%5,%6,%7}, {%8,%9}, {%0,%1,%2,%3};"
        : "+f"(d[0]), "+f"(d[1]), "+f"(d[2]), "+f"(d[3])
        : "r"(a[0]), "r"(a[1]), "r"(a[2]), "r"(a[3]), "r"(b0), "r"(b1));
}
__device__ __forceinline__ void cp16(uint32_t saddr, const void* g) {
    asm volatile("cp.async.cg.shared.global [%0], [%1], 16;" :: "r"(saddr), "l"(g));
}
#define CP_COMMIT() asm volatile("cp.async.commit_group;" ::: "memory")
#define CP_WAIT1()  asm volatile("cp.async.wait_group 1;" ::: "memory")
#define CP_WAIT0()  asm volatile("cp.async.wait_group 0;" ::: "memory")

// pack 8 floats -> hi uint4 (8 bf16) and lo uint4
__device__ __forceinline__ void split8(const float* v, uint4& hi, uint4& lo) {
    __nv_bfloat16 h[8], l[8];
    #pragma unroll
    for (int e = 0; e < 8; e++) {
        h[e] = __float2bfloat16(v[e]);
        l[e] = __float2bfloat16(v[e] - __bfloat162float(h[e]));
    }
    hi = *(uint4*)h;
    lo = *(uint4*)l;
}

// ---------------- stage 0: avgpool x->f, mask->m ----------------
__global__ void k_avgpool(const float* __restrict__ x, const float* __restrict__ mask) {
    int idx = blockIdx.x * blockDim.x + threadIdx.x;
    const int total = Bsz * hh * ww * Cc;
    if (idx < total) {
        int c = idx % Cc;
        int j = (idx / Cc) % ww;
        int i = (idx / (Cc * ww)) % hh;
        int b = idx / (Cc * ww * hh);
        const float* xb = x + (size_t)b * Hf * Wf * Cc;
        float s = xb[((2*i)   * Wf + 2*j  ) * Cc + c]
                + xb[((2*i)   * Wf + 2*j+1) * Cc + c]
                + xb[((2*i+1) * Wf + 2*j  ) * Cc + c]
                + xb[((2*i+1) * Wf + 2*j+1) * Cc + c];
        g_f[idx] = 0.25f * s;
    }
    if (idx < Bsz * hh * ww) {
        int j = idx % ww;
        int i = (idx / ww) % hh;
        int b = idx / (ww * hh);
        const float* mb = mask + (size_t)b * Hf * Wf;
        float s = mb[(2*i)*Wf + 2*j] + mb[(2*i)*Wf + 2*j+1]
                + mb[(2*i+1)*Wf + 2*j] + mb[(2*i+1)*Wf + 2*j+1];
        g_m[idx] = 0.25f * s;
    }
}

// ---------------- stage 1: im2col of f -> bf16 hi/lo (8 channels/thread) ----------------
__global__ void k_im2col_f8() {
    int idx = blockIdx.x * blockDim.x + threadIdx.x;
    const int total = Bsz * Ll * (KK / 8);   // 589824
    if (idx >= total) return;
    int k8 = idx % 72;
    int p  = (idx / 72) % Ll;
    int b  = idx / (72 * Ll);
    int c0 = (k8 & 7) * 8;
    int dw = (k8 >> 3) % 3;
    int dh = k8 / 24;
    int i = p >> 6, j = p & 63;
    int ri = i - 1 + dh, rj = j - 1 + dw;
    float v[8];
    if (ri >= 0 && ri < hh && rj >= 0 && rj < ww) {
        const float4* src = (const float4*)&g_f[(((size_t)b * hh + ri) * ww + rj) * Cc + c0];
        *(float4*)&v[0] = src[0];
        *(float4*)&v[4] = src[1];
    } else {
        #pragma unroll
        for (int e = 0; e < 8; e++) v[e] = 0.f;
    }
    uint4 hi, lo;
    split8(v, hi, lo);
    size_t off = ((size_t)b * Ll + p) * KK + k8 * 8;
    *(uint4*)&g_Phi[off] = hi;
    *(uint4*)&g_Plo[off] = lo;
}

// ---------------- stage 2: im2col of raw x -> bf16 hi/lo (8 channels/thread) ----------------
__global__ void k_im2col_raw8(const float* __restrict__ x) {
    int idx = blockIdx.x * blockDim.x + threadIdx.x;
    const int total = Bsz * Ll * (KK / 8);
    if (idx >= total) return;
    int k8 = idx % 72;
    int p  = (idx / 72) % Ll;
    int b  = idx / (72 * Ll);
    int c0 = (k8 & 7) * 8;
    int dw = (k8 >> 3) % 3;
    int dh = k8 / 24;
    int i = p >> 6, j = p & 63;
    int ri = 2*i + dh, rj = 2*j + dw;   // pad bottom/right only
    float v[8];
    if (ri < Hf && rj < Wf) {
        const float4* src = (const float4*)&x[(((size_t)b * Hf + ri) * Wf + rj) * Cc + c0];
        *(float4*)&v[0] = src[0];
        *(float4*)&v[4] = src[1];
    } else {
        #pragma unroll
        for (int e = 0; e < 8; e++) v[e] = 0.f;
    }
    uint4 hi, lo;
    split8(v, hi, lo);
    size_t off = ((size_t)b * Ll + p) * KK + k8 * 8;
    *(uint4*)&g_Rhi[off] = hi;
    *(uint4*)&g_Rlo[off] = lo;
}

// ---------------- stage 3a: per-pixel sum of squares ----------------
__global__ void k_pixssq() {
    int idx = blockIdx.x * blockDim.x + threadIdx.x;
    if (idx >= Bsz * Ll) return;
    const float4* row = (const float4*)&g_f[(size_t)idx * Cc];
    float s = 0.f;
    #pragma unroll
    for (int c = 0; c < 16; c++) {
        float4 v = row[c];
        s += v.x*v.x + v.y*v.y + v.z*v.z + v.w*v.w;
    }
    g_ssq[idx] = s;
}

// ---------------- stage 3b: norm = 3x3 box sum of ssq ----------------
__global__ void k_normbox() {
    int idx = blockIdx.x * blockDim.x + threadIdx.x;
    if (idx >= Bsz * Ll) return;
    int q = idx % Ll;
    int b = idx / Ll;
    int i = q >> 6, j = q & 63;
    float s = 0.f;
    #pragma unroll
    for (int dh = 0; dh < 3; dh++)
        #pragma unroll
        for (int dw = 0; dw < 3; dw++) {
            int ri = i - 1 + dh, rj = j - 1 + dw;
            if (ri >= 0 && ri < hh && rj >= 0 && rj < ww)
                s += g_ssq[b * Ll + ri * ww + rj];
        }
    g_rn[idx] = 1.0f / fmaxf(sqrtf(s), 1e-4f);
}

// ---------------- stage 4: mask gate ----------------
__global__ void k_mmgate() {
    int idx = blockIdx.x * blockDim.x + threadIdx.x;
    if (idx >= Bsz * Ll) return;
    int q = idx % Ll;
    int b = idx / Ll;
    int i = q >> 6, j = q & 63;
    float s = 0.f;
    for (int dh = 0; dh < 3; dh++)
        for (int dw = 0; dw < 3; dw++) {
            int ri = i - 1 + dh, rj = j - 1 + dw;
            if (ri >= 0 && ri < hh && rj >= 0 && rj < ww)
                s += g_m[((size_t)b * hh + ri) * ww + rj];
        }
    g_mm[idx] = ((s / 9.0f) == 1.0f) ? 1.0f : 0.0f;
}

// ---------------- stage 4b: compact gated columns ----------------
__global__ __launch_bounds__(256) void k_compact() {
    int b = blockIdx.x;
    __shared__ int cnts[256];
    __shared__ int offs[257];
    int t = threadIdx.x;
    const float* mmb = g_mm + b * Ll;
    int base = t * 16;
    int local = 0;
    #pragma unroll
    for (int e = 0; e < 16; e++) local += (mmb[base + e] != 0.f) ? 1 : 0;
    cnts[t] = local;
    __syncthreads();
    if (t == 0) {
        int run = 0;
        for (int s = 0; s < 256; s++) { offs[s] = run; run += cnts[s]; }
        offs[256] = run;
        g_cnt[b] = run;
    }
    __syncthreads();
    int o = offs[t];
    int* idxb = g_idxl + b * Ll;
    #pragma unroll
    for (int e = 0; e < 16; e++)
        if (mmb[base + e] != 0.f) idxb[o++] = base + e;
}

// ---------------- stage 5: GEMM1 (mma.sync bf16 hi/lo, cp.async double-buffered) ----------------
#define PITCH 72
#define ARR_B (128 * PITCH * 2)       // 18432 bytes per array
#define STAGE_B (4 * ARR_B)           // 73728 per stage
#define G1_SMEM (2 * STAGE_B)         // 147456
__global__ __launch_bounds__(256, 1) void k_gemm1_mma(float* __restrict__ att) {
    int b  = blockIdx.z;
    int bi = blockIdx.y;
    int bj = blockIdx.x;
    if (bj < bi) return;

    extern __shared__ char sm[];
    uint32_t uS = smem_u32(sm);

    int tid = threadIdx.x;
    int wid = tid >> 5;
    int lane = tid & 31;
    int mw = wid >> 2;       // 0..1
    int nw = wid & 3;        // 0..3

    const __nv_bfloat16* Phi = g_Phi + (size_t)b * Ll * KK;
    const __nv_bfloat16* Plo = g_Plo + (size_t)b * Ll * KK;
    int pBase = bi * 128, qBase = bj * 128;

    float d[4][4][4];
    #pragma unroll
    for (int mi = 0; mi < 4; mi++)
        #pragma unroll
        for (int ni = 0; ni < 4; ni++)
            #pragma unroll
            for (int e = 0; e < 4; e++) d[mi][ni][e] = 0.f;

    int aRow = lane & 15;
    int aKof = ((lane >> 4) & 1) * 8;
    int bGrp = lane >> 3;
    int bLr  = lane & 7;
    int bNt  = bGrp >> 1;
    int bKof = (bGrp & 1) * 8;

    // issue loads for chunk ch into stage st
    auto issue = [&](int ch, int st) {
        int k0 = ch * 64;
        uint32_t ub = uS + st * STAGE_B;
        #pragma unroll
        for (int it = 0; it < 4; it++) {
            int idx = it * 256 + tid;
            int row = idx >> 3;
            int c4  = idx & 7;
            size_t goffA = (size_t)(pBase + row) * KK + k0 + c4 * 8;
            size_t goffB = (size_t)(qBase + row) * KK + k0 + c4 * 8;
            uint32_t so = (uint32_t)(row * PITCH + c4 * 8) * 2;
            cp16(ub + so,             &Phi[goffA]);
            cp16(ub + ARR_B + so,     &Plo[goffA]);
            cp16(ub + 2 * ARR_B + so, &Phi[goffB]);
            cp16(ub + 3 * ARR_B + so, &Plo[goffB]);
        }
        CP_COMMIT();
    };

    issue(0, 0);
    #pragma unroll 1
    for (int ch = 0; ch < 9; ch++) {
        int s = ch & 1;
        if (ch + 1 < 9) { issue(ch + 1, (ch + 1) & 1); CP_WAIT1(); }
        else            { CP_WAIT0(); }
        __syncthreads();

        uint32_t uAhi = uS + s * STAGE_B;
        uint32_t uAlo = uAhi + ARR_B;
        uint32_t uBhi = uAhi + 2 * ARR_B;
        uint32_t uBlo = uAhi + 3 * ARR_B;

        #pragma unroll
        for (int ks = 0; ks < 4; ks++) {
            uint32_t ah[4][4], al[4][4], bhr[2][4], blr[2][4];
            #pragma unroll
            for (int mi = 0; mi < 4; mi++) {
                uint32_t off = ((mw * 64 + mi * 16 + aRow) * PITCH + ks * 16 + aKof) * 2;
                ldsm_x4(ah[mi][0], ah[mi][1], ah[mi][2], ah[mi][3], uAhi + off);
                ldsm_x4(al[mi][0], al[mi][1], al[mi][2], al[mi][3], uAlo + off);
            }
            #pragma unroll
            for (int np = 0; np < 2; np++) {
                uint32_t off = ((nw * 32 + np * 16 + bNt * 8 + bLr) * PITCH + ks * 16 + bKof) * 2;
                ldsm_x4(bhr[np][0], bhr[np][1], bhr[np][2], bhr[np][3], uBhi + off);
                ldsm_x4(blr[np][0], blr[np][1], blr[np][2], blr[np][3], uBlo + off);
            }
            #pragma unroll
            for (int mi = 0; mi < 4; mi++)
                #pragma unroll
                for (int ni = 0; ni < 4; ni++) {
                    uint32_t bh0 = bhr[ni >> 1][(ni & 1) * 2];
                    uint32_t bh1 = bhr[ni >> 1][(ni & 1) * 2 + 1];
                    uint32_t bl0 = blr[ni >> 1][(ni & 1) * 2];
                    uint32_t bl1 = blr[ni >> 1][(ni & 1) * 2 + 1];
                    mma_bf16(d[mi][ni], ah[mi], bh0, bh1);
                    mma_bf16(d[mi][ni], ah[mi], bl0, bl1);
                    mma_bf16(d[mi][ni], al[mi], bh0, bh1);
                }
        }
        __syncthreads();
    }

    // epilogue: fragments -> smem C[128][129]
    float* Csh = (float*)sm;
    #pragma unroll
    for (int mi = 0; mi < 4; mi++)
        #pragma unroll
        for (int ni = 0; ni < 4; ni++) {
            int r0 = mw * 64 + mi * 16 + (lane >> 2);
            int c0 = nw * 32 + ni * 8 + (lane & 3) * 2;
            Csh[r0 * 129 + c0]       = d[mi][ni][0];
            Csh[r0 * 129 + c0 + 1]   = d[mi][ni][1];
            Csh[(r0 + 8) * 129 + c0]     = d[mi][ni][2];
            Csh[(r0 + 8) * 129 + c0 + 1] = d[mi][ni][3];
        }
    __syncthreads();

    const float* rn = g_rn + b * Ll;
    float* Cmat = att + (size_t)b * ATT_PER_B;
    int row = tid & 127;
    int half = tid >> 7;
    {
        float4* dst = (float4*)&Cmat[(size_t)(pBase + row) * Ll + qBase + half * 64];
        const float4* rq = (const float4*)(rn + qBase + half * 64);
        const float* src = &Csh[row * 129 + half * 64];
        #pragma unroll
        for (int j = 0; j < 16; j++) {
            float4 rv = rq[j];
            float4 v;
            v.x = src[4*j + 0] * rv.x;
            v.y = src[4*j + 1] * rv.y;
            v.z = src[4*j + 2] * rv.z;
            v.w = src[4*j + 3] * rv.w;
            dst[j] = v;
        }
    }
    if (bi != bj) {
        float4* dst = (float4*)&Cmat[(size_t)(qBase + row) * Ll + pBase + half * 64];
        const float4* rp = (const float4*)(rn + pBase + half * 64);
        #pragma unroll
        for (int j = 0; j < 16; j++) {
            float4 rv = rp[j];
            int c = half * 64 + 4 * j;
            float4 v;
            v.x = Csh[(c + 0) * 129 + row] * rv.x;
            v.y = Csh[(c + 1) * 129 + row] * rv.y;
            v.z = Csh[(c + 2) * 129 + row] * rv.z;
            v.w = Csh[(c + 3) * 129 + row] * rv.w;
            dst[j] = v;
        }
    }
}

// ---------------- stage 6: fuse + softmax over gated columns -> bf16 hi/lo compacted ----------------
__global__ __launch_bounds__(256) void k_fuse_softmax(const float* __restrict__ att) {
    int b = blockIdx.y;
    int p = blockIdx.x;
    const float* Sb  = att + (size_t)b * ATT_PER_B;
    int cnt = g_cnt[b];
    const int* idxb = g_idxl + b * Ll;
    __nv_bfloat16* Ahi = g_Ahi + ((size_t)b * Ll + p) * Ll;
    __nv_bfloat16* Alo = g_Alo + ((size_t)b * Ll + p) * Ll;

    __shared__ float zrow[Ll];
    __shared__ float red[256];

    int i = p >> 6, j = p & 63;
    int t = j * 64 + i;

    int  Pb[3] = {0, 0, 0};
    bool pv[3];
    #pragma unroll
    for (int d = 0; d < 3; d++) {
        int tb = t + d - 1;
        pv[d] = (tb >= 0 && tb < Ll);
        if (pv[d]) Pb[d] = ((tb & 63) << 6) | (tb >> 6);
    }

    float lmax = (cnt < Ll) ? 0.0f : -3.4e38f;
    for (int k = threadIdx.x; k < cnt; k += 256) {
        int q = idxb[k];
        int u = ((q & 63) << 6) | (q >> 6);
        float acc = 0.f;
        #pragma unroll
        for (int d = 0; d < 3; d++) {
            int ub = u + d - 1;
            if (pv[d] && ub >= 0 && ub < Ll) {
                int Q = ((ub & 63) << 6) | (ub >> 6);
                int P = Pb[d];
                #pragma unroll
                for (int a = -1; a <= 1; a++) {
                    int Pa = P + a, Qa = Q + a;
                    if (Pa >= 0 && Pa < Ll && Qa >= 0 && Qa < Ll)
                        acc += Sb[(size_t)Pa * Ll + Qa];
                }
            }
        }
        float val = acc * 10.0f;
        zrow[k] = val;
        lmax = fmaxf(lmax, val);
    }
    red[threadIdx.x] = lmax;
    __syncthreads();
    for (int s = 128; s > 0; s >>= 1) {
        if (threadIdx.x < s) red[threadIdx.x] = fmaxf(red[threadIdx.x], red[threadIdx.x + s]);
        __syncthreads();
    }
    float mx = red[0];
    __syncthreads();

    float lsum = 0.f;
    for (int k = threadIdx.x; k < cnt; k += 256) {
        float e = __expf(zrow[k] - mx);
        zrow[k] = e;
        lsum += e;
    }
    red[threadIdx.x] = lsum;
    __syncthreads();
    for (int s = 128; s > 0; s >>= 1) {
        if (threadIdx.x < s) red[threadIdx.x] += red[threadIdx.x + s];
        __syncthreads();
    }
    float denom = red[0] + (float)(Ll - cnt) * __expf(-mx);
    float inv = 1.0f / denom;
    for (int k = threadIdx.x; k < cnt; k += 256) {
        float v = zrow[k] * inv;
        __nv_bfloat16 hv = __float2bfloat16(v);
        Ahi[k] = hv;
        Alo[k] = __float2bfloat16(v - __bfloat162float(hv));
    }
    int kp64 = (cnt + 63) & ~63;
    for (int k = cnt + (int)threadIdx.x; k < kp64; k += 256) {
        Ahi[k] = __float2bfloat16(0.f);
        Alo[k] = __float2bfloat16(0.f);
    }
}

// ---------------- stage 7: GEMM2 via mma.sync bf16 hi/lo ----------------
#define A2_B (128 * PITCH * 2)   // 18432
#define B2_B (64 * PITCH * 2)    // 9216
#define G2_SMEM (2 * A2_B + 2 * B2_B)  // 55296
__global__ __launch_bounds__(256, 2) void k_gemm2_mma() {
    int b  = blockIdx.z;
    int bm = blockIdx.y;   // 0..31
    int bn = blockIdx.x;   // 0..8
    int cnt = g_cnt[b];
    int kp = (cnt + 63) & ~63;
    const int* idxb = g_idxl + b * Ll;
    const __nv_bfloat16* Ahi = g_Ahi + (size_t)b * Ll * Ll;
    const __nv_bfloat16* Alo = g_Alo + (size_t)b * Ll * Ll;
    const __nv_bfloat16* Rhi = g_Rhi + (size_t)b * Ll * KK;
    const __nv_bfloat16* Rlo = g_Rlo + (size_t)b * Ll * KK;
    float* Cm = g_M + (size_t)b * Ll * KK;

    extern __shared__ char sm2[];
    __nv_bfloat16* sAh = (__nv_bfloat16*)(sm2);
    __nv_bfloat16* sAl = (__nv_bfloat16*)(sm2 + A2_B);
    __nv_bfloat16* sBh = (__nv_bfloat16*)(sm2 + 2 * A2_B);
    __nv_bfloat16* sBl = (__nv_bfloat16*)(sm2 + 2 * A2_B + B2_B);
    uint32_t uAh = smem_u32(sAh), uAl = smem_u32(sAl);
    uint32_t uBh = smem_u32(sBh), uBl = smem_u32(sBl);

    int tid = threadIdx.x;
    int wid = tid >> 5;
    int lane = tid & 31;
    int mw = wid >> 1;
    int nw = wid & 1;
    int mBase = bm * 128, nBase = bn * 64;

    float d[2][4][4];
    #pragma unroll
    for (int mi = 0; mi < 2; mi++)
        #pragma unroll
        for (int ni = 0; ni < 4; ni++)
            #pragma unroll
            for (int e = 0; e < 4; e++) d[mi][ni][e] = 0.f;

    int aRow = lane & 15;
    int aKof = ((lane >> 4) & 1) * 8;
    int bGrp = lane >> 3;
    int bLr  = lane & 7;
    int bNt  = bGrp >> 1;
    int bKof = (bGrp & 1) * 8;

    int arow = tid >> 1, ahalf = tid & 1;
    int kg = tid & 63, seg = tid >> 6;

    #pragma unroll 1
    for (int k0 = 0; k0 < kp; k0 += 64) {
        {   // A tile via cp.async
            uint32_t so = (uint32_t)(arow * PITCH + ahalf * 32) * 2;
            const char* pH = (const char*)&Ahi[(size_t)(mBase + arow) * Ll + k0 + ahalf * 32];
            const char* pL = (const char*)&Alo[(size_t)(mBase + arow) * Ll + k0 + ahalf * 32];
            #pragma unroll
            for (int jj = 0; jj < 4; jj++) {
                cp16(uAh + so + jj * 16, pH + jj * 16);
                cp16(uAl + so + jj * 16, pL + jj * 16);
            }
            CP_COMMIT();
        }
        {   // B tile: gather row idx[k0+kg], transpose-store Bs[n][kg]
            int krow = (k0 + kg < cnt) ? idxb[k0 + kg] : 0;
            const uint4* pH = (const uint4*)&Rhi[(size_t)krow * KK + nBase + seg * 16];
            const uint4* pL = (const uint4*)&Rlo[(size_t)krow * KK + nBase + seg * 16];
            __nv_bfloat16 th[16], tl[16];
            *(uint4*)&th[0] = pH[0]; *(uint4*)&th[8] = pH[1];
            *(uint4*)&tl[0] = pL[0]; *(uint4*)&tl[8] = pL[1];
            #pragma unroll
            for (int n = 0; n < 16; n++) {
                sBh[(seg * 16 + n) * PITCH + kg] = th[n];
                sBl[(seg * 16 + n) * PITCH + kg] = tl[n];
            }
        }
        CP_WAIT0();
        __syncthreads();

        #pragma unroll
        for (int ks = 0; ks < 4; ks++) {
            uint32_t ah[2][4], al[2][4], bhr[2][4], blr[2][4];
            #pragma unroll
            for (int mi = 0; mi < 2; mi++) {
                uint32_t off = ((mw * 32 + mi * 16 + aRow) * PITCH + ks * 16 + aKof) * 2;
                ldsm_x4(ah[mi][0], ah[mi][1], ah[mi][2], ah[mi][3], uAh + off);
                ldsm_x4(al[mi][0], al[mi][1], al[mi][2], al[mi][3], uAl + off);
            }
            #pragma unroll
            for (int np = 0; np < 2; np++) {
                uint32_t off = ((nw * 32 + np * 16 + bNt * 8 + bLr) * PITCH + ks * 16 + bKof) * 2;
                ldsm_x4(bhr[np][0], bhr[np][1], bhr[np][2], bhr[np][3], uBh + off);
                ldsm_x4(blr[np][0], blr[np][1], blr[np][2], blr[np][3], uBl + off);
            }
            #pragma unroll
            for (int mi = 0; mi < 2; mi++)
                #pragma unroll
                for (int ni = 0; ni < 4; ni++) {
                    uint32_t bh0 = bhr[ni >> 1][(ni & 1) * 2];
                    uint32_t bh1 = bhr[ni >> 1][(ni & 1) * 2 + 1];
                    uint32_t bl0 = blr[ni >> 1][(ni & 1) * 2];
                    uint32_t bl1 = blr[ni >> 1][(ni & 1) * 2 + 1];
                    mma_bf16(d[mi][ni], ah[mi], bh0, bh1);
                    mma_bf16(d[mi][ni], ah[mi], bl0, bl1);
                    mma_bf16(d[mi][ni], al[mi], bh0, bh1);
                }
        }
        __syncthreads();
    }

    #pragma unroll
    for (int mi = 0; mi < 2; mi++)
        #pragma unroll
        for (int ni = 0; ni < 4; ni++) {
            int r0 = mBase + mw * 32 + mi * 16 + (lane >> 2);
            int c0 = nBase + nw * 32 + ni * 8 + (lane & 3) * 2;
            *(float2*)&Cm[(size_t)r0 * KK + c0]       = make_float2(d[mi][ni][0], d[mi][ni][1]);
            *(float2*)&Cm[(size_t)(r0 + 8) * KK + c0] = make_float2(d[mi][ni][2], d[mi][ni][3]);
        }
}

// ---------------- stage 8: scatter (adjoint of stride-2 SAME conv), /4 ----------------
__global__ void k_scatter(float* __restrict__ y) {
    int idx = blockIdx.x * blockDim.x + threadIdx.x;
    const int total = Bsz * Hf * Wf * (Cc / 4);
    if (idx >= total) return;
    int c4 = idx & 15;
    int qq = (idx >> 4) & 127;
    int pp = (idx >> 11) & 127;
    int b  = idx >> 18;

    const float* Mb = g_M + (size_t)b * Ll * KK;

    int icand[2], khc[2], nci = 0;
    if ((pp & 1) == 0) {
        icand[nci] = pp >> 1; khc[nci] = 0; nci++;
        if (pp >= 2) { icand[nci] = (pp >> 1) - 1; khc[nci] = 2; nci++; }
    } else { icand[0] = pp >> 1; khc[0] = 1; nci = 1; }

    int jcand[2], kwc[2], ncj = 0;
    if ((qq & 1) == 0) {
        jcand[ncj] = qq >> 1; kwc[ncj] = 0; ncj++;
        if (qq >= 2) { jcand[ncj] = (qq >> 1) - 1; kwc[ncj] = 2; ncj++; }
    } else { jcand[0] = qq >> 1; kwc[0] = 1; ncj = 1; }

    float4 s = make_float4(0.f, 0.f, 0.f, 0.f);
    for (int a = 0; a < nci; a++)
        for (int c = 0; c < ncj; c++) {
            const float4 v = *(const float4*)&Mb[(size_t)(icand[a] * 64 + jcand[c]) * KK
                                                 + (khc[a] * 3 + kwc[c]) * 64 + c4 * 4];
            s.x += v.x; s.y += v.y; s.z += v.z; s.w += v.w;
        }
    s.x *= 0.25f; s.y *= 0.25f; s.z *= 0.25f; s.w *= 0.25f;
    ((float4*)y)[idx] = s;
}

// ---------------- launch ----------------
extern "C" void kernel_launch(void* const* d_in, const int* in_sizes, int n_in,
                              void* d_out, int out_size) {
    const float* x    = (const float*)d_in[0];
    const float* mask = (const float*)d_in[1];
    float* out = (float*)d_out;
    float* y   = out;
    float* att = out + Y_ELEMS;

    cudaFuncSetAttribute(k_gemm1_mma, cudaFuncAttributeMaxDynamicSharedMemorySize, G1_SMEM);
    cudaFuncSetAttribute(k_gemm2_mma, cudaFuncAttributeMaxDynamicSharedMemorySize, G2_SMEM);

    k_avgpool   <<<(Bsz*hh*ww*Cc + 255) / 256, 256>>>(x, mask);
    k_im2col_f8 <<<(Bsz*Ll*(KK/8) + 255) / 256, 256>>>();
    k_im2col_raw8<<<(Bsz*Ll*(KK/8) + 255) / 256, 256>>>(x);
    k_pixssq    <<<(Bsz*Ll + 255) / 256, 256>>>();
    k_normbox   <<<(Bsz*Ll + 255) / 256, 256>>>();
    k_mmgate    <<<(Bsz*Ll + 255) / 256, 256>>>();
    k_compact   <<<Bsz, 256>>>();
    k_gemm1_mma <<<dim3(32, 32, Bsz), 256, G1_SMEM>>>(att);
    k_fuse_softmax<<<dim3(Ll, Bsz), 256>>>(att);
    k_gemm2_mma <<<dim3(9, 32, Bsz), 256, G2_SMEM>>>();
    k_scatter   <<<(Bsz*Hf*Wf*16 + 255) / 256, 256>>>(y);
}